// round 1
// baseline (speedup 1.0000x reference)
#include <cuda_runtime.h>
#include <cstdint>
#include <math.h>

// ---------------- constants ----------------
#define PI_F      3.14159265358979323846f
#define PI2_F     9.86960440108935861883f   // pi^2
#define THIRD_F   2.09439510239319549231f   // 2*pi/3
#define DEVPI_F   0.003183098861837907f     // 0.01/pi
#define SQRTD_F   22.62741699796952f        // sqrt(512)

constexpr int S  = 512;
constexpr int D  = 512;
constexpr int H  = 8;
constexpr int DH = 64;
constexpr int L  = 6;
constexpr int F  = 2048;
constexpr int BB = 16;
constexpr int MT = BB * S;   // 8192 tokens
constexpr int BH = BB * H;   // 128 (batch*heads)

// ---------------- device scratch (static, allocation-free) ----------------
__device__ float d_x   [MT * D];
__device__ float d_qkv [MT * 3 * D];
__device__ float d_sc  [(size_t)BH * S * S];   // 33.5M floats
__device__ float d_ao  [MT * D];
__device__ float d_ff  [MT * F];
__device__ float d_tmp [MT * D];
__device__ float d_wi  [3 * D * D];
__device__ float d_w1  [F * D];
__device__ float d_w2  [D * F];
__device__ float d_abs [F * D];
__device__ unsigned d_h1[4096];
__device__ unsigned d_h2[2 * 65536];
__device__ unsigned d_h3[32];
__device__ unsigned d_sel[8];
__device__ float d_thr;

// ---------------- generic register-tiled GEMM ----------------
// C[m,n] = alpha * sum_k A[m,k] * (TB ? B[n,k] : B[k,n])  (+bias[n]) (+relu)
// batch via grid.z with two-level strides: z1 = bz/zdiv, z2 = bz%zdiv
template<int BM,int BN,int BK,int TM,int TN,bool TB,bool RELU>
__global__ void __launch_bounds__((BM/TM)*(BN/TN))
k_gemm(int M, int N, int K,
       const float* __restrict__ Ag, int lda, long long sA1, long long sA2,
       const float* __restrict__ Bg, int ldb, long long sB1, long long sB2,
       float* __restrict__ Cg, int ldc, long long sC1, long long sC2,
       int zdiv, const float* __restrict__ bias, float alpha)
{
    constexpr int NT = (BM/TM)*(BN/TN);
    constexpr int LA = (BM*BK)/NT;
    constexpr int LB = (BN*BK)/NT;
    __shared__ float As[BK][BM+4];
    __shared__ float Bs[BK][BN+4];

    const int bz = blockIdx.z;
    const int z1 = bz / zdiv, z2 = bz - z1*zdiv;
    const float* A  = Ag + z1*sA1 + z2*sA2;
    const float* Bp = Bg + z1*sB1 + z2*sB2;
    float* C        = Cg + z1*sC1 + z2*sC2;

    const int m0 = blockIdx.y * BM, n0 = blockIdx.x * BN;
    const int tid = threadIdx.x;
    const int tx = tid % (BN/TN), ty = tid / (BN/TN);

    float acc[TM][TN];
    #pragma unroll
    for (int i = 0; i < TM; i++)
        #pragma unroll
        for (int j = 0; j < TN; j++) acc[i][j] = 0.f;

    for (int k0 = 0; k0 < K; k0 += BK) {
        #pragma unroll
        for (int r = 0; r < LA; r++) {
            int i = tid + r*NT;
            int m = i / BK, kk = i - m*BK;
            int gm = m0 + m;
            As[kk][m] = (gm < M) ? A[(long long)gm*lda + k0 + kk] : 0.f;
        }
        if (TB) {
            #pragma unroll
            for (int r = 0; r < LB; r++) {
                int i = tid + r*NT;
                int n = i / BK, kk = i - n*BK;
                int gn = n0 + n;
                Bs[kk][n] = (gn < N) ? Bp[(long long)gn*ldb + k0 + kk] : 0.f;
            }
        } else {
            #pragma unroll
            for (int r = 0; r < LB; r++) {
                int i = tid + r*NT;
                int kk = i / BN, n = i - kk*BN;
                int gn = n0 + n;
                Bs[kk][n] = (gn < N) ? Bp[(long long)(k0+kk)*ldb + gn] : 0.f;
            }
        }
        __syncthreads();
        #pragma unroll
        for (int kk = 0; kk < BK; kk++) {
            float ar[TM], br[TN];
            #pragma unroll
            for (int i = 0; i < TM; i += 4) {
                float4 t = *reinterpret_cast<const float4*>(&As[kk][ty*TM + i]);
                ar[i]=t.x; ar[i+1]=t.y; ar[i+2]=t.z; ar[i+3]=t.w;
            }
            #pragma unroll
            for (int j = 0; j < TN; j += 4) {
                float4 t = *reinterpret_cast<const float4*>(&Bs[kk][tx*TN + j]);
                br[j]=t.x; br[j+1]=t.y; br[j+2]=t.z; br[j+3]=t.w;
            }
            #pragma unroll
            for (int i = 0; i < TM; i++)
                #pragma unroll
                for (int j = 0; j < TN; j++)
                    acc[i][j] += ar[i]*br[j];
        }
        __syncthreads();
    }
    #pragma unroll
    for (int i = 0; i < TM; i++) {
        int gm = m0 + ty*TM + i;
        if (gm >= M) continue;
        #pragma unroll
        for (int j = 0; j < TN; j++) {
            int gn = n0 + tx*TN + j;
            if (gn >= N) continue;
            float v = acc[i][j] * alpha;
            if (bias) v += bias[gn];
            if (RELU) v = fmaxf(v, 0.f);
            C[(long long)gm*ldc + gn] = v;
        }
    }
}

// ---------------- softmax over rows of 512 ----------------
__global__ void k_softmax(float* __restrict__ sc)
{
    long long row = blockIdx.x;
    float* r = sc + row * S;
    int t = threadIdx.x;
    float v0 = r[t], v1 = r[t + 256];
    __shared__ float red[256];
    red[t] = fmaxf(v0, v1); __syncthreads();
    for (int o = 128; o > 0; o >>= 1) { if (t < o) red[t] = fmaxf(red[t], red[t+o]); __syncthreads(); }
    float m = red[0]; __syncthreads();
    float e0 = expf(v0 - m), e1 = expf(v1 - m);
    red[t] = e0 + e1; __syncthreads();
    for (int o = 128; o > 0; o >>= 1) { if (t < o) red[t] += red[t+o]; __syncthreads(); }
    float inv = 1.f / red[0];
    r[t] = e0 * inv; r[t + 256] = e1 * inv;
}

// ---------------- fused residual add + layernorm ----------------
__global__ void k_add_ln(const float* __restrict__ xin, const float* __restrict__ res,
                         const float* __restrict__ g, const float* __restrict__ b,
                         float* __restrict__ xout)
{
    int row = blockIdx.x, t = threadIdx.x;
    long long base = (long long)row * D;
    float v0 = xin[base + t]       + res[base + t];
    float v1 = xin[base + t + 256] + res[base + t + 256];
    __shared__ float red[256];
    red[t] = v0 + v1; __syncthreads();
    for (int o = 128; o > 0; o >>= 1) { if (t < o) red[t] += red[t+o]; __syncthreads(); }
    float mean = red[0] * (1.f / D); __syncthreads();
    red[t] = v0*v0 + v1*v1; __syncthreads();
    for (int o = 128; o > 0; o >>= 1) { if (t < o) red[t] += red[t+o]; __syncthreads(); }
    float var = red[0] * (1.f / D) - mean*mean;
    float rs = rsqrtf(var + 1e-5f);
    xout[base + t]       = (v0 - mean) * rs * g[t]       + b[t];
    xout[base + t + 256] = (v1 - mean) * rs * g[t + 256] + b[t + 256];
}

// ---------------- embedding + positional ----------------
__global__ void k_embed(const int* __restrict__ src, const float* __restrict__ emb,
                        const float* __restrict__ pos, float* __restrict__ x)
{
    int idx = blockIdx.x * blockDim.x + threadIdx.x;
    int t = idx >> 9, d = idx & 511;
    x[idx] = emb[(long long)src[t] * D + d] * SQRTD_F + pos[(t & 511) * D + d];
}

// ---------------- prune pipeline ----------------
__global__ void k_zero()
{
    int i = blockIdx.x * blockDim.x + threadIdx.x;
    if (i < 131072) d_h2[i] = 0;
    if (i < 4096)   d_h1[i] = 0;
    if (i < 32)     d_h3[i] = 0;
}

// etch: |cos(bloom*pi^2) + bloom^2*(0.01/pi)| with bloom = clip(sin(w*pi)) * (1 + 1.5*cos(i/(s-1) + 2pi/3))
__global__ void k_etch(const float* __restrict__ w, int n, float inv_sm1)
{
    __shared__ unsigned h[4096];
    for (int j = threadIdx.x; j < 4096; j += blockDim.x) h[j] = 0;
    __syncthreads();
    int stride = gridDim.x * blockDim.x;
    for (int i = blockIdx.x * blockDim.x + threadIdx.x; i < n; i += stride) {
        float wv = w[i];
        float b0 = sinf(wv * PI_F);
        b0 = fminf(fmaxf(b0, -1.f), 1.f);
        float bl = b0 + b0 * cosf((float)i * inv_sm1 + THIRD_F) * 1.5f;
        float e = cosf(bl * PI2_F) + bl * bl * DEVPI_F;
        float a = fabsf(e);
        d_abs[i] = a;
        atomicAdd(&h[__float_as_uint(a) >> 20], 1u);
    }
    __syncthreads();
    for (int j = threadIdx.x; j < 4096; j += blockDim.x) {
        unsigned c = h[j];
        if (c) atomicAdd(&d_h1[j], c);
    }
}

__global__ void k_scan1(unsigned rA, unsigned rB)
{
    __shared__ unsigned part[256];
    __shared__ unsigned pref[256];
    int t = threadIdx.x, base = t * 16;
    unsigned c[16]; unsigned s = 0;
    for (int j = 0; j < 16; j++) { c[j] = d_h1[base + j]; s += c[j]; }
    part[t] = s; __syncthreads();
    if (t == 0) { unsigned a = 0; for (int i = 0; i < 256; i++) { pref[i] = a; a += part[i]; } }
    __syncthreads();
    unsigned p = pref[t];
    for (int j = 0; j < 16; j++) {
        if (rA >= p && rA < p + c[j]) { d_sel[0] = base + j; d_sel[1] = rA - p; }
        if (rB >= p && rB < p + c[j]) { d_sel[2] = base + j; d_sel[3] = rB - p; }
        p += c[j];
    }
}

__global__ void k_hist2(int n)
{
    unsigned sA = d_sel[0], sB = d_sel[2];
    int stride = gridDim.x * blockDim.x;
    for (int i = blockIdx.x * blockDim.x + threadIdx.x; i < n; i += stride) {
        unsigned u = __float_as_uint(d_abs[i]);
        unsigned hi = u >> 20, mid = (u >> 4) & 0xFFFFu;
        if (hi == sA) atomicAdd(&d_h2[mid], 1u);
        if (hi == sB) atomicAdd(&d_h2[65536 + mid], 1u);
    }
}

__global__ void k_scan2()
{
    __shared__ unsigned part[256];
    __shared__ unsigned pref[256];
    int t = threadIdx.x;
    for (int sidx = 0; sidx < 2; sidx++) {
        unsigned rank = d_sel[1 + sidx * 2];
        const unsigned* hb = d_h2 + sidx * 65536;
        int base = t * 256;
        unsigned s = 0;
        for (int j = 0; j < 256; j++) s += hb[base + j];
        part[t] = s; __syncthreads();
        if (t == 0) { unsigned a = 0; for (int i = 0; i < 256; i++) { pref[i] = a; a += part[i]; } }
        __syncthreads();
        unsigned p = pref[t];
        for (int j = 0; j < 256; j++) {
            unsigned c = hb[base + j];
            if (rank >= p && rank < p + c) { d_sel[4 + sidx*2] = base + j; d_sel[5 + sidx*2] = rank - p; }
            p += c;
        }
        __syncthreads();
    }
}

__global__ void k_hist3(int n)
{
    unsigned kA = (d_sel[0] << 16) | d_sel[4];
    unsigned kB = (d_sel[2] << 16) | d_sel[6];
    int stride = gridDim.x * blockDim.x;
    for (int i = blockIdx.x * blockDim.x + threadIdx.x; i < n; i += stride) {
        unsigned u = __float_as_uint(d_abs[i]);
        unsigned top = u >> 4;
        if (top == kA) atomicAdd(&d_h3[u & 15u], 1u);
        if (top == kB) atomicAdd(&d_h3[16 + (u & 15u)], 1u);
    }
}

__global__ void k_thr(float frac)
{
    if (threadIdx.x == 0) {
        unsigned remA = d_sel[5]; unsigned lowA = 0;
        for (int j = 0; j < 16; j++) { unsigned c = d_h3[j]; if (remA < c) { lowA = j; break; } remA -= c; }
        unsigned remB = d_sel[7]; unsigned lowB = 0;
        for (int j = 0; j < 16; j++) { unsigned c = d_h3[16 + j]; if (remB < c) { lowB = j; break; } remB -= c; }
        float vA = __uint_as_float((d_sel[0] << 20) | (d_sel[4] << 4) | lowA);
        float vB = __uint_as_float((d_sel[2] << 20) | (d_sel[6] << 4) | lowB);
        d_thr = vA + frac * (vB - vA);
    }
}

__global__ void k_mask(const float* __restrict__ w, int n, float* __restrict__ out)
{
    int i = blockIdx.x * blockDim.x + threadIdx.x;
    if (i < n) out[i] = (d_abs[i] > d_thr) ? w[i] : 0.f;
}

// ---------------- host-side prune helper (enqueues 8 kernels) ----------------
static void prune_w(const float* w, int s, float* out)
{
    k_zero<<<512, 256>>>();
    k_etch<<<512, 256>>>(w, s, 1.f / (float)(s - 1));
    double r = 0.25 * (double)(s - 1);
    unsigned kA = (unsigned)r;
    float frac = (float)(r - (double)kA);
    k_scan1<<<1, 256>>>(kA, kA + 1);
    k_hist2<<<512, 256>>>(s);
    k_scan2<<<1, 256>>>();
    k_hist3<<<512, 256>>>(s);
    k_thr<<<1, 32>>>(frac);
    k_mask<<<(s + 255) / 256, 256>>>(w, s, out);
}

// ---------------- entry point ----------------
extern "C" void kernel_launch(void* const* d_in, const int* in_sizes, int n_in,
                              void* d_out, int out_size)
{
    const int*   src = (const int*)  d_in[0];
    const float* emb = (const float*)d_in[1];
    const float* pos = (const float*)d_in[2];
    const float* ipw = (const float*)d_in[3];
    const float* ipb = (const float*)d_in[4];
    const float* opw = (const float*)d_in[5];
    const float* opb = (const float*)d_in[6];
    const float* l1g = (const float*)d_in[7];
    const float* l1b = (const float*)d_in[8];
    const float* l2g = (const float*)d_in[9];
    const float* l2b = (const float*)d_in[10];
    const float* w1  = (const float*)d_in[11];
    const float* b1  = (const float*)d_in[12];
    const float* w2  = (const float*)d_in[13];
    const float* b2  = (const float*)d_in[14];
    const float* ow  = (const float*)d_in[15];
    const float* ob  = (const float*)d_in[16];
    const int V = in_sizes[16];
    float* out = (float*)d_out;

    float *px, *pqkv, *psc, *pao, *pff, *ptmp, *pwi, *pw1, *pw2;
    cudaGetSymbolAddress((void**)&px,   d_x);
    cudaGetSymbolAddress((void**)&pqkv, d_qkv);
    cudaGetSymbolAddress((void**)&psc,  d_sc);
    cudaGetSymbolAddress((void**)&pao,  d_ao);
    cudaGetSymbolAddress((void**)&pff,  d_ff);
    cudaGetSymbolAddress((void**)&ptmp, d_tmp);
    cudaGetSymbolAddress((void**)&pwi,  d_wi);
    cudaGetSymbolAddress((void**)&pw1,  d_w1);
    cudaGetSymbolAddress((void**)&pw2,  d_w2);

    // x = emb[src]*sqrt(D) + pos
    k_embed<<<MT * D / 256, 256>>>(src, emb, pos, px);

    for (int l = 0; l < L; l++) {
        // --- attention block ---
        prune_w(ipw + (size_t)l * 3 * D * D, 3 * D * D, pwi);
        // qkv = x @ wi^T + b
        k_gemm<128,128,8,8,8,true,false><<<dim3((3*D)/128, MT/128, 1), 256>>>(
            MT, 3*D, D, px, D, 0, 0, pwi, D, 0, 0, pqkv, 3*D, 0, 0, 1,
            ipb + (size_t)l * 3 * D, 1.f);
        // scores = Q K^T / 8   (batched over b,h)
        k_gemm<128,128,8,8,8,true,false><<<dim3(S/128, S/128, BH), 256>>>(
            S, S, DH,
            pqkv,     3*D, (long long)S*3*D, DH,
            pqkv + D, 3*D, (long long)S*3*D, DH,
            psc, S, (long long)H*S*S, (long long)S*S,
            H, nullptr, 0.125f);
        // softmax rows
        k_softmax<<<BH * S, 256>>>(psc);
        // o = att @ V
        k_gemm<128,64,8,8,4,false,false><<<dim3(1, S/128, BH), 256>>>(
            S, DH, S,
            psc, S, (long long)H*S*S, (long long)S*S,
            pqkv + 2*D, 3*D, (long long)S*3*D, DH,
            pao, D, (long long)S*D, DH,
            H, nullptr, 1.f);
        // out projection
        k_gemm<128,128,8,8,8,true,false><<<dim3(D/128, MT/128, 1), 256>>>(
            MT, D, D, pao, D, 0, 0, opw + (size_t)l*D*D, D, 0, 0,
            ptmp, D, 0, 0, 1, opb + (size_t)l*D, 1.f);
        // x = LN(x + o)
        k_add_ln<<<MT, 256>>>(px, ptmp, l1g + (size_t)l*D, l1b + (size_t)l*D, px);

        // --- feed-forward block ---
        prune_w(w1 + (size_t)l * F * D, F * D, pw1);
        k_gemm<128,128,8,8,8,true,true><<<dim3(F/128, MT/128, 1), 256>>>(
            MT, F, D, px, D, 0, 0, pw1, D, 0, 0, pff, F, 0, 0, 1,
            b1 + (size_t)l*F, 1.f);
        prune_w(w2 + (size_t)l * D * F, D * F, pw2);
        k_gemm<128,128,8,8,8,true,false><<<dim3(D/128, MT/128, 1), 256>>>(
            MT, D, F, pff, F, 0, 0, pw2, F, 0, 0, ptmp, D, 0, 0, 1,
            b2 + (size_t)l*D, 1.f);
        k_add_ln<<<MT, 256>>>(px, ptmp, l2g + (size_t)l*D, l2b + (size_t)l*D, px);
    }

    // logits = x @ out_w^T + out_b  -> directly to d_out
    k_gemm<128,128,8,8,8,true,false><<<dim3((V + 127) / 128, MT / 128, 1), 256>>>(
        MT, V, D, px, D, 0, 0, ow, D, 0, 0, out, V, 0, 0, 1, ob, 1.f);
}

// round 2
// speedup vs baseline: 2.1621x; 2.1621x over previous
#include <cuda_runtime.h>
#include <cstdint>
#include <math.h>

// ---------------- constants ----------------
#define PI_F      3.14159265358979323846f
#define PI2_F     9.86960440108935861883f   // pi^2
#define THIRD_F   2.09439510239319549231f   // 2*pi/3
#define DEVPI_F   0.003183098861837907f     // 0.01/pi
#define SQRTD_F   22.62741699796952f        // sqrt(512)

constexpr int S  = 512;
constexpr int D  = 512;
constexpr int H  = 8;
constexpr int DH = 64;
constexpr int L  = 6;
constexpr int F  = 2048;
constexpr int BB = 16;
constexpr int MT = BB * S;   // 8192 tokens
constexpr int BH = BB * H;   // 128 (batch*heads)
constexpr int NSLOT = 18;    // 3 weight types * 6 layers
constexpr size_t SLOT_STRIDE = 1048576;  // max weight elems (F*D)

// ---------------- device scratch (static, allocation-free) ----------------
__device__ float d_x   [MT * D];
__device__ float d_qkv [MT * 3 * D];
__device__ float d_sc  [(size_t)BH * S * S];
__device__ float d_ao  [MT * D];
__device__ float d_ff  [MT * F];
__device__ float d_tmp [MT * D];
__device__ float d_wp     [NSLOT * SLOT_STRIDE];   // pruned weights
__device__ float d_abs_all[NSLOT * SLOT_STRIDE];
__device__ unsigned d_h1g[NSLOT * 4096];
__device__ unsigned d_h2g[NSLOT * 2 * 65536];
__device__ unsigned d_h3g[NSLOT * 32];
__device__ unsigned d_selg[NSLOT * 8];
__device__ float d_thrg[NSLOT];

// ---------------- tf32 helpers ----------------
__device__ __forceinline__ uint32_t f2tf(float f) {
    uint32_t u;
    asm("cvt.rna.tf32.f32 %0, %1;" : "=r"(u) : "f"(f));
    return u;
}

__device__ __forceinline__ void mma_tf32(float c[4],
    uint32_t a0, uint32_t a1, uint32_t a2, uint32_t a3,
    uint32_t b0, uint32_t b1)
{
    asm volatile(
        "mma.sync.aligned.m16n8k8.row.col.f32.tf32.tf32.f32 "
        "{%0,%1,%2,%3}, {%4,%5,%6,%7}, {%8,%9}, {%0,%1,%2,%3};"
        : "+f"(c[0]), "+f"(c[1]), "+f"(c[2]), "+f"(c[3])
        : "r"(a0), "r"(a1), "r"(a2), "r"(a3), "r"(b0), "r"(b1));
}

// ---------------- tensor-core GEMM ----------------
// C[m,n] = alpha * sum_k A[m,k] * (TB ? B[n,k] : B[k,n])  (+bias[n]) (+relu)
// batch via grid.z: z1 = bz/zdiv, z2 = bz%zdiv
// Requires: BK==32, M % BM == 0, K % BK == 0; if !GN also N % BN == 0.
template<int BM,int BN,int BK,int WARPS_M,int WARPS_N,bool TB,bool RELU,bool GN>
__global__ void __launch_bounds__(WARPS_M*WARPS_N*32)
k_mma(int M, int N, int K,
      const float* __restrict__ Ag, int lda, long long sA1, long long sA2,
      const float* __restrict__ Bg, int ldb, long long sB1, long long sB2,
      float* __restrict__ Cg, int ldc, long long sC1, long long sC2,
      int zdiv, const float* __restrict__ bias, float alpha)
{
    constexpr int NT  = WARPS_M * WARPS_N * 32;
    constexpr int WM  = BM / WARPS_M;
    constexpr int WN  = BN / WARPS_N;
    constexpr int MT_ = WM / 16;
    constexpr int NT_ = WN / 8;
    constexpr int PB  = TB ? 1 : 4;

    __shared__ uint32_t As[BK][BM + 1];
    __shared__ uint32_t Bs[BK][BN + PB];

    const int bz = blockIdx.z;
    const int z1 = bz / zdiv, z2 = bz - z1 * zdiv;
    const float* A  = Ag + z1 * sA1 + z2 * sA2;
    const float* Bp = Bg + z1 * sB1 + z2 * sB2;
    float* C        = Cg + z1 * sC1 + z2 * sC2;

    const int m0 = blockIdx.y * BM, n0 = blockIdx.x * BN;
    const int tid  = threadIdx.x;
    const int lane = tid & 31, warp = tid >> 5;
    const int wm = warp / WARPS_N, wn = warp - wm * WARPS_N;
    const int g = lane >> 2, t4 = lane & 3;

    float acc[MT_][NT_][4];
    #pragma unroll
    for (int i = 0; i < MT_; i++)
        #pragma unroll
        for (int j = 0; j < NT_; j++)
            #pragma unroll
            for (int q = 0; q < 4; q++) acc[i][j][q] = 0.f;

    for (int k0 = 0; k0 < K; k0 += BK) {
        // ---- load A tile (row-major [M,K]) ----
        constexpr int LA4 = (BM * BK / 4) / NT;
        #pragma unroll
        for (int r = 0; r < LA4; r++) {
            int i = tid + r * NT;
            int m  = i >> 3;          // BK/4 == 8
            int k4 = (i & 7) << 2;
            float4 v = *reinterpret_cast<const float4*>(
                &A[(size_t)(m0 + m) * lda + k0 + k4]);
            As[k4][m]     = f2tf(v.x);
            As[k4 + 1][m] = f2tf(v.y);
            As[k4 + 2][m] = f2tf(v.z);
            As[k4 + 3][m] = f2tf(v.w);
        }
        // ---- load B tile ----
        if (TB) {  // B row-major [N,K]
            constexpr int LB4 = (BN * BK / 4) / NT;
            #pragma unroll
            for (int r = 0; r < LB4; r++) {
                int i = tid + r * NT;
                int n  = i >> 3;
                int k4 = (i & 7) << 2;
                int gn = n0 + n;
                float4 v;
                if (GN && gn >= N) v = make_float4(0.f, 0.f, 0.f, 0.f);
                else v = *reinterpret_cast<const float4*>(
                    &Bp[(size_t)gn * ldb + k0 + k4]);
                Bs[k4][n]     = f2tf(v.x);
                Bs[k4 + 1][n] = f2tf(v.y);
                Bs[k4 + 2][n] = f2tf(v.z);
                Bs[k4 + 3][n] = f2tf(v.w);
            }
        } else {   // B row-major [K,N]
            constexpr int LB4 = (BK * BN / 4) / NT;
            #pragma unroll
            for (int r = 0; r < LB4; r++) {
                int i = tid + r * NT;
                int kk = i / (BN / 4);
                int n4 = (i - kk * (BN / 4)) * 4;
                float4 v = *reinterpret_cast<const float4*>(
                    &Bp[(size_t)(k0 + kk) * ldb + n0 + n4]);
                uint4 u;
                u.x = f2tf(v.x); u.y = f2tf(v.y); u.z = f2tf(v.z); u.w = f2tf(v.w);
                *reinterpret_cast<uint4*>(&Bs[kk][n4]) = u;
            }
        }
        __syncthreads();

        // ---- compute ----
        #pragma unroll
        for (int ks = 0; ks < BK / 8; ks++) {
            uint32_t af[MT_][4];
            uint32_t bf[NT_][2];
            #pragma unroll
            for (int i = 0; i < MT_; i++) {
                int mr = wm * WM + i * 16 + g;
                af[i][0] = As[ks * 8 + t4][mr];
                af[i][1] = As[ks * 8 + t4][mr + 8];
                af[i][2] = As[ks * 8 + t4 + 4][mr];
                af[i][3] = As[ks * 8 + t4 + 4][mr + 8];
            }
            #pragma unroll
            for (int j = 0; j < NT_; j++) {
                int nc = wn * WN + j * 8 + g;
                bf[j][0] = Bs[ks * 8 + t4][nc];
                bf[j][1] = Bs[ks * 8 + t4 + 4][nc];
            }
            #pragma unroll
            for (int i = 0; i < MT_; i++)
                #pragma unroll
                for (int j = 0; j < NT_; j++)
                    mma_tf32(acc[i][j], af[i][0], af[i][1], af[i][2], af[i][3],
                             bf[j][0], bf[j][1]);
        }
        __syncthreads();
    }

    // ---- epilogue ----
    #pragma unroll
    for (int i = 0; i < MT_; i++) {
        int r0 = m0 + wm * WM + i * 16 + g;
        #pragma unroll
        for (int j = 0; j < NT_; j++) {
            int col = n0 + wn * WN + j * 8 + t4 * 2;
            if (GN && col >= N) continue;
            float b0v = 0.f, b1v = 0.f;
            if (bias) { b0v = bias[col]; b1v = bias[col + 1]; }
            float v0 = acc[i][j][0] * alpha + b0v;
            float v1 = acc[i][j][1] * alpha + b1v;
            float v2 = acc[i][j][2] * alpha + b0v;
            float v3 = acc[i][j][3] * alpha + b1v;
            if (RELU) {
                v0 = fmaxf(v0, 0.f); v1 = fmaxf(v1, 0.f);
                v2 = fmaxf(v2, 0.f); v3 = fmaxf(v3, 0.f);
            }
            *reinterpret_cast<float2*>(&C[(size_t)r0 * ldc + col])       = make_float2(v0, v1);
            *reinterpret_cast<float2*>(&C[(size_t)(r0 + 8) * ldc + col]) = make_float2(v2, v3);
        }
    }
}

// ---------------- softmax over rows of 512 ----------------
__global__ void k_softmax(float* __restrict__ sc)
{
    long long row = blockIdx.x;
    float* r = sc + row * S;
    int t = threadIdx.x;
    float v0 = r[t], v1 = r[t + 256];
    __shared__ float red[256];
    red[t] = fmaxf(v0, v1); __syncthreads();
    for (int o = 128; o > 0; o >>= 1) { if (t < o) red[t] = fmaxf(red[t], red[t+o]); __syncthreads(); }
    float m = red[0]; __syncthreads();
    float e0 = expf(v0 - m), e1 = expf(v1 - m);
    red[t] = e0 + e1; __syncthreads();
    for (int o = 128; o > 0; o >>= 1) { if (t < o) red[t] += red[t+o]; __syncthreads(); }
    float inv = 1.f / red[0];
    r[t] = e0 * inv; r[t + 256] = e1 * inv;
}

// ---------------- fused residual add + layernorm ----------------
__global__ void k_add_ln(const float* __restrict__ xin, const float* __restrict__ res,
                         const float* __restrict__ g, const float* __restrict__ b,
                         float* __restrict__ xout)
{
    int row = blockIdx.x, t = threadIdx.x;
    long long base = (long long)row * D;
    float v0 = xin[base + t]       + res[base + t];
    float v1 = xin[base + t + 256] + res[base + t + 256];
    __shared__ float red[256];
    red[t] = v0 + v1; __syncthreads();
    for (int o = 128; o > 0; o >>= 1) { if (t < o) red[t] += red[t+o]; __syncthreads(); }
    float mean = red[0] * (1.f / D); __syncthreads();
    red[t] = v0*v0 + v1*v1; __syncthreads();
    for (int o = 128; o > 0; o >>= 1) { if (t < o) red[t] += red[t+o]; __syncthreads(); }
    float var = red[0] * (1.f / D) - mean*mean;
    float rs = rsqrtf(var + 1e-5f);
    xout[base + t]       = (v0 - mean) * rs * g[t]       + b[t];
    xout[base + t + 256] = (v1 - mean) * rs * g[t + 256] + b[t + 256];
}

// ---------------- embedding + positional ----------------
__global__ void k_embed(const int* __restrict__ src, const float* __restrict__ emb,
                        const float* __restrict__ pos, float* __restrict__ x)
{
    int idx = blockIdx.x * blockDim.x + threadIdx.x;
    int t = idx >> 9, d = idx & 511;
    x[idx] = emb[(long long)src[t] * D + d] * SQRTD_F + pos[(t & 511) * D + d];
}

// ---------------- batched prune pipeline (18 slots) ----------------
// slot = type*6 + layer; type 0: in_proj (3D*D), 1: lin1 (F*D), 2: lin2 (D*F)
__device__ __forceinline__ const float* slot_w(int slot, const float* ipw,
                                               const float* w1, const float* w2, int& n)
{
    int t = slot / 6, l = slot - t * 6;
    if (t == 0) { n = 3 * D * D; return ipw + (size_t)l * 3 * D * D; }
    n = F * D;
    return (t == 1) ? w1 + (size_t)l * F * D : w2 + (size_t)l * F * D;
}

__global__ void k_zero_all()
{
    int i = blockIdx.x * blockDim.x + threadIdx.x;
    if (i < NSLOT * 2 * 65536) d_h2g[i] = 0;
    if (i < NSLOT * 4096)      d_h1g[i] = 0;
    if (i < NSLOT * 32)        d_h3g[i] = 0;
}

__global__ void k_etch_all(const float* __restrict__ ipw, const float* __restrict__ w1,
                           const float* __restrict__ w2)
{
    int slot = blockIdx.y;
    int n;
    const float* w = slot_w(slot, ipw, w1, w2, n);
    float inv = 1.f / (float)(n - 1);
    float* aout = d_abs_all + (size_t)slot * SLOT_STRIDE;
    unsigned* h1 = d_h1g + slot * 4096;

    __shared__ unsigned h[4096];
    for (int j = threadIdx.x; j < 4096; j += blockDim.x) h[j] = 0;
    __syncthreads();
    int stride = gridDim.x * blockDim.x;
    for (int i = blockIdx.x * blockDim.x + threadIdx.x; i < n; i += stride) {
        float wv = w[i];
        float b0 = sinf(wv * PI_F);
        b0 = fminf(fmaxf(b0, -1.f), 1.f);
        float bl = b0 + b0 * cosf((float)i * inv + THIRD_F) * 1.5f;
        float e = cosf(bl * PI2_F) + bl * bl * DEVPI_F;
        float a = fabsf(e);
        aout[i] = a;
        atomicAdd(&h[__float_as_uint(a) >> 20], 1u);
    }
    __syncthreads();
    for (int j = threadIdx.x; j < 4096; j += blockDim.x) {
        unsigned c = h[j];
        if (c) atomicAdd(&h1[j], c);
    }
}

__global__ void k_scan1_all(const float* ipw, const float* w1, const float* w2)
{
    int slot = blockIdx.x;
    int n; slot_w(slot, ipw, w1, w2, n);
    unsigned rA = (unsigned)((n - 1) >> 2);  // floor(0.25*(n-1))
    unsigned rB = rA + 1;
    const unsigned* h1 = d_h1g + slot * 4096;
    unsigned* sel = d_selg + slot * 8;

    __shared__ unsigned part[256];
    __shared__ unsigned pref[256];
    int t = threadIdx.x, base = t * 16;
    unsigned c[16]; unsigned s = 0;
    for (int j = 0; j < 16; j++) { c[j] = h1[base + j]; s += c[j]; }
    part[t] = s; __syncthreads();
    if (t == 0) { unsigned a = 0; for (int i = 0; i < 256; i++) { pref[i] = a; a += part[i]; } }
    __syncthreads();
    unsigned p = pref[t];
    for (int j = 0; j < 16; j++) {
        if (rA >= p && rA < p + c[j]) { sel[0] = base + j; sel[1] = rA - p; }
        if (rB >= p && rB < p + c[j]) { sel[2] = base + j; sel[3] = rB - p; }
        p += c[j];
    }
}

__global__ void k_hist2_all(const float* ipw, const float* w1, const float* w2)
{
    int slot = blockIdx.y;
    int n; slot_w(slot, ipw, w1, w2, n);
    const float* ab = d_abs_all + (size_t)slot * SLOT_STRIDE;
    const unsigned* sel = d_selg + slot * 8;
    unsigned* h2 = d_h2g + (size_t)slot * 131072;
    unsigned sA = sel[0], sB = sel[2];
    int stride = gridDim.x * blockDim.x;
    for (int i = blockIdx.x * blockDim.x + threadIdx.x; i < n; i += stride) {
        unsigned u = __float_as_uint(ab[i]);
        unsigned hi = u >> 20, mid = (u >> 4) & 0xFFFFu;
        if (hi == sA) atomicAdd(&h2[mid], 1u);
        if (hi == sB) atomicAdd(&h2[65536 + mid], 1u);
    }
}

__global__ void k_scan2_all()
{
    int slot = blockIdx.x;
    unsigned* sel = d_selg + slot * 8;
    __shared__ unsigned part[256];
    __shared__ unsigned pref[256];
    int t = threadIdx.x;
    for (int sidx = 0; sidx < 2; sidx++) {
        unsigned rank = sel[1 + sidx * 2];
        const unsigned* hb = d_h2g + (size_t)slot * 131072 + sidx * 65536;
        int base = t * 256;
        unsigned s = 0;
        for (int j = 0; j < 256; j++) s += hb[base + j];
        part[t] = s; __syncthreads();
        if (t == 0) { unsigned a = 0; for (int i = 0; i < 256; i++) { pref[i] = a; a += part[i]; } }
        __syncthreads();
        unsigned p = pref[t];
        for (int j = 0; j < 256; j++) {
            unsigned c = hb[base + j];
            if (rank >= p && rank < p + c) { sel[4 + sidx*2] = base + j; sel[5 + sidx*2] = rank - p; }
            p += c;
        }
        __syncthreads();
    }
}

__global__ void k_hist3_all(const float* ipw, const float* w1, const float* w2)
{
    int slot = blockIdx.y;
    int n; slot_w(slot, ipw, w1, w2, n);
    const float* ab = d_abs_all + (size_t)slot * SLOT_STRIDE;
    const unsigned* sel = d_selg + slot * 8;
    unsigned* h3 = d_h3g + slot * 32;
    unsigned kA = (sel[0] << 16) | sel[4];
    unsigned kB = (sel[2] << 16) | sel[6];
    int stride = gridDim.x * blockDim.x;
    for (int i = blockIdx.x * blockDim.x + threadIdx.x; i < n; i += stride) {
        unsigned u = __float_as_uint(ab[i]);
        unsigned top = u >> 4;
        if (top == kA) atomicAdd(&h3[u & 15u], 1u);
        if (top == kB) atomicAdd(&h3[16 + (u & 15u)], 1u);
    }
}

__global__ void k_thr_all(const float* ipw, const float* w1, const float* w2)
{
    int slot = blockIdx.x * blockDim.x + threadIdx.x;
    if (slot >= NSLOT) return;
    int n; slot_w(slot, ipw, w1, w2, n);
    float frac = 0.25f * (float)((n - 1) & 3);
    const unsigned* sel = d_selg + slot * 8;
    const unsigned* h3 = d_h3g + slot * 32;
    unsigned remA = sel[5]; unsigned lowA = 0;
    for (int j = 0; j < 16; j++) { unsigned c = h3[j]; if (remA < c) { lowA = j; break; } remA -= c; }
    unsigned remB = sel[7]; unsigned lowB = 0;
    for (int j = 0; j < 16; j++) { unsigned c = h3[16 + j]; if (remB < c) { lowB = j; break; } remB -= c; }
    float vA = __uint_as_float((sel[0] << 20) | (sel[4] << 4) | lowA);
    float vB = __uint_as_float((sel[2] << 20) | (sel[6] << 4) | lowB);
    d_thrg[slot] = vA + frac * (vB - vA);
}

__global__ void k_mask_all(const float* __restrict__ ipw, const float* __restrict__ w1,
                           const float* __restrict__ w2)
{
    int slot = blockIdx.y;
    int n;
    const float* w = slot_w(slot, ipw, w1, w2, n);
    int i = blockIdx.x * blockDim.x + threadIdx.x;
    if (i >= n) return;
    float thr = d_thrg[slot];
    d_wp[(size_t)slot * SLOT_STRIDE + i] =
        (d_abs_all[(size_t)slot * SLOT_STRIDE + i] > thr) ? w[i] : 0.f;
}

// ---------------- entry point ----------------
extern "C" void kernel_launch(void* const* d_in, const int* in_sizes, int n_in,
                              void* d_out, int out_size)
{
    const int*   src = (const int*)  d_in[0];
    const float* emb = (const float*)d_in[1];
    const float* pos = (const float*)d_in[2];
    const float* ipw = (const float*)d_in[3];
    const float* ipb = (const float*)d_in[4];
    const float* opw = (const float*)d_in[5];
    const float* opb = (const float*)d_in[6];
    const float* l1g = (const float*)d_in[7];
    const float* l1b = (const float*)d_in[8];
    const float* l2g = (const float*)d_in[9];
    const float* l2b = (const float*)d_in[10];
    const float* w1  = (const float*)d_in[11];
    const float* b1  = (const float*)d_in[12];
    const float* w2  = (const float*)d_in[13];
    const float* b2  = (const float*)d_in[14];
    const float* ow  = (const float*)d_in[15];
    const float* ob  = (const float*)d_in[16];
    const int V = in_sizes[16];
    float* out = (float*)d_out;

    float *px, *pqkv, *psc, *pao, *pff, *ptmp, *pwp;
    cudaGetSymbolAddress((void**)&px,   d_x);
    cudaGetSymbolAddress((void**)&pqkv, d_qkv);
    cudaGetSymbolAddress((void**)&psc,  d_sc);
    cudaGetSymbolAddress((void**)&pao,  d_ao);
    cudaGetSymbolAddress((void**)&pff,  d_ff);
    cudaGetSymbolAddress((void**)&ptmp, d_tmp);
    cudaGetSymbolAddress((void**)&pwp,  d_wp);

    // embedding
    k_embed<<<MT * D / 256, 256>>>(src, emb, pos, px);

    // ---- prune all 18 weight matrices up-front (8 launches total) ----
    k_zero_all<<<(NSLOT * 2 * 65536 + 255) / 256, 256>>>();
    k_etch_all <<<dim3(128, NSLOT), 256>>>(ipw, w1, w2);
    k_scan1_all<<<NSLOT, 256>>>(ipw, w1, w2);
    k_hist2_all<<<dim3(128, NSLOT), 256>>>(ipw, w1, w2);
    k_scan2_all<<<NSLOT, 256>>>();
    k_hist3_all<<<dim3(128, NSLOT), 256>>>(ipw, w1, w2);
    k_thr_all  <<<1, 32>>>(ipw, w1, w2);
    k_mask_all <<<dim3(4096, NSLOT), 256>>>(ipw, w1, w2);

    for (int l = 0; l < L; l++) {
        const float* wi_l = pwp + (size_t)(0 * 6 + l) * SLOT_STRIDE;
        const float* w1_l = pwp + (size_t)(1 * 6 + l) * SLOT_STRIDE;
        const float* w2_l = pwp + (size_t)(2 * 6 + l) * SLOT_STRIDE;

        // qkv = x @ wi^T + b   [8192 x 1536]
        k_mma<128,128,32,2,4,true,false,false><<<dim3((3*D)/128, MT/128, 1), 256>>>(
            MT, 3*D, D, px, D, 0, 0, wi_l, D, 0, 0, pqkv, 3*D, 0, 0, 1,
            ipb + (size_t)l * 3 * D, 1.f);
        // scores = Q K^T / 8   (batched over b,h)
        k_mma<128,128,32,2,4,true,false,false><<<dim3(S/128, S/128, BH), 256>>>(
            S, S, DH,
            pqkv,     3*D, (long long)S*3*D, DH,
            pqkv + D, 3*D, (long long)S*3*D, DH,
            psc, S, (long long)H*S*S, (long long)S*S,
            H, nullptr, 0.125f);
        k_softmax<<<BH * S, 256>>>(psc);
        // o = att @ V   [512 x 64] per bh
        k_mma<128,64,32,2,2,false,false,false><<<dim3(1, S/128, BH), 128>>>(
            S, DH, S,
            psc, S, (long long)H*S*S, (long long)S*S,
            pqkv + 2*D, 3*D, (long long)S*3*D, DH,
            pao, D, (long long)S*D, DH,
            H, nullptr, 1.f);
        // out projection
        k_mma<128,128,32,2,4,true,false,false><<<dim3(D/128, MT/128, 1), 256>>>(
            MT, D, D, pao, D, 0, 0, opw + (size_t)l*D*D, D, 0, 0,
            ptmp, D, 0, 0, 1, opb + (size_t)l*D, 1.f);
        k_add_ln<<<MT, 256>>>(px, ptmp, l1g + (size_t)l*D, l1b + (size_t)l*D, px);

        // feed-forward
        k_mma<128,128,32,2,4,true,true,false><<<dim3(F/128, MT/128, 1), 256>>>(
            MT, F, D, px, D, 0, 0, w1_l, D, 0, 0, pff, F, 0, 0, 1,
            b1 + (size_t)l*F, 1.f);
        k_mma<128,128,32,2,4,true,false,false><<<dim3(D/128, MT/128, 1), 256>>>(
            MT, D, F, pff, F, 0, 0, w2_l, F, 0, 0, ptmp, D, 0, 0, 1,
            b2 + (size_t)l*D, 1.f);
        k_add_ln<<<MT, 256>>>(px, ptmp, l2g + (size_t)l*D, l2b + (size_t)l*D, px);
    }

    // logits = x @ out_w^T + out_b  (N=10000, guarded)
    k_mma<128,128,32,2,4,true,false,true><<<dim3((V + 127) / 128, MT / 128, 1), 256>>>(
        MT, V, D, px, D, 0, 0, ow, D, 0, 0, out, V, 0, 0, 1, ob, 1.f);
}

// round 3
// speedup vs baseline: 3.6961x; 1.7094x over previous
#include <cuda_runtime.h>
#include <cstdint>
#include <math.h>

// ---------------- constants ----------------
#define PI_F      3.14159265358979323846f
#define PI2_F     9.86960440108935861883f
#define THIRD_F   2.09439510239319549231f
#define DEVPI_F   0.003183098861837907f
#define SQRTD_F   22.62741699796952f

constexpr int S  = 512;
constexpr int D  = 512;
constexpr int H  = 8;
constexpr int DH = 64;
constexpr int L  = 6;
constexpr int F  = 2048;
constexpr int BB = 16;
constexpr int MT = BB * S;   // 8192 tokens
constexpr int BH = BB * H;   // 128
constexpr int NSLOT = 18;
constexpr size_t SLOT_STRIDE = 1048576;
constexpr int VMAX = 10240;

// ---------------- device scratch ----------------
__device__ __align__(128) float d_x   [MT * D];
__device__ __align__(128) float d_xtf [MT * D];     // tf32-rounded copy of x
__device__ __align__(128) float d_qkv [MT * 3 * D];
__device__ __align__(128) float d_sc  [(size_t)BH * S * S];
__device__ __align__(128) float d_ao  [MT * D];
__device__ __align__(128) float d_ff  [MT * F];
__device__ __align__(128) float d_tmp [MT * D];
__device__ __align__(128) float d_wp  [NSLOT * SLOT_STRIDE];
__device__ __align__(128) float d_wr  [L * D * D];      // rounded out_proj_w
__device__ __align__(128) float d_owr [VMAX * D];       // rounded out_w
__device__ __align__(128) float d_abs_all[NSLOT * SLOT_STRIDE];
__device__ unsigned d_h1g[NSLOT * 4096];
__device__ unsigned d_h2g[NSLOT * 2 * 65536];
__device__ unsigned d_h3g[NSLOT * 32];
__device__ unsigned d_selg[NSLOT * 8];
__device__ float d_thrg[NSLOT];

// ---------------- helpers ----------------
__device__ __forceinline__ float tf32r(float f) {
    uint32_t u;
    asm("cvt.rna.tf32.f32 %0, %1;" : "=r"(u) : "f"(f));
    return __uint_as_float(u);
}

__device__ __forceinline__ void mma_tf32(float c[4],
    uint32_t a0, uint32_t a1, uint32_t a2, uint32_t a3,
    uint32_t b0, uint32_t b1)
{
    asm volatile(
        "mma.sync.aligned.m16n8k8.row.col.f32.tf32.tf32.f32 "
        "{%0,%1,%2,%3}, {%4,%5,%6,%7}, {%8,%9}, {%0,%1,%2,%3};"
        : "+f"(c[0]), "+f"(c[1]), "+f"(c[2]), "+f"(c[3])
        : "r"(a0), "r"(a1), "r"(a2), "r"(a3), "r"(b0), "r"(b1));
}

__device__ __forceinline__ void cp16(void* d, const void* s) {
    uint32_t a = (uint32_t)__cvta_generic_to_shared(d);
    asm volatile("cp.async.cg.shared.global [%0], [%1], 16;" :: "r"(a), "l"(s));
}
__device__ __forceinline__ void cp16p(void* d, const void* s, bool p) {
    uint32_t a = (uint32_t)__cvta_generic_to_shared(d);
    int sz = p ? 16 : 0;
    asm volatile("cp.async.cg.shared.global [%0], [%1], 16, %2;" :: "r"(a), "l"(s), "r"(sz));
}
#define CP_COMMIT() asm volatile("cp.async.commit_group;")
#define CP_WAIT1()  asm volatile("cp.async.wait_group 1;")

// ---------------- pipelined tensor-core GEMM ----------------
// C[m,n] = alpha * sum_k A[m,k] * (TB ? B[n,k] : B[k,n])  (+bias) (+relu)
// ALL operands must already be tf32-rounded fp32. BK == 16.
template<int BM,int BN,int WARPS_M,int WARPS_N,bool TB,bool RELU,bool GN,bool TFO>
__global__ void __launch_bounds__(WARPS_M*WARPS_N*32)
k_mma(int M, int N, int K,
      const float* __restrict__ Ag, int lda, long long sA1, long long sA2,
      const float* __restrict__ Bg, int ldb, long long sB1, long long sB2,
      float* __restrict__ Cg, int ldc, long long sC1, long long sC2,
      int zdiv, const float* __restrict__ bias, float alpha)
{
    constexpr int BK = 16;
    constexpr int NT = WARPS_M * WARPS_N * 32;
    constexpr int WM = BM / WARPS_M, WN = BN / WARPS_N;
    constexpr int MI = WM / 16, NI = WN / 8;
    constexpr int AST = BK + 4;                 // 20: %32==4 -> conflict-free frags
    constexpr int BROWS = TB ? BN : BK;
    constexpr int BCOLS = TB ? (BK + 4) : (BN + 8);  // 20 or BN+8 (%32==8)

    __shared__ __align__(16) float As[2][BM][AST];
    __shared__ __align__(16) float Bs[2][BROWS][BCOLS];

    const int bz = blockIdx.z;
    const int z1 = bz / zdiv, z2 = bz - z1 * zdiv;
    const float* A  = Ag + z1 * sA1 + z2 * sA2;
    const float* Bp = Bg + z1 * sB1 + z2 * sB2;
    float* C        = Cg + z1 * sC1 + z2 * sC2;

    const int m0 = blockIdx.y * BM, n0 = blockIdx.x * BN;
    const int tid  = threadIdx.x;
    const int lane = tid & 31, warp = tid >> 5;
    const int wm = warp / WARPS_N, wn = warp - wm * WARPS_N;
    const int g = lane >> 2, t4 = lane & 3;

    float acc[MI][NI][4];
    #pragma unroll
    for (int i = 0; i < MI; i++)
        #pragma unroll
        for (int j = 0; j < NI; j++)
            #pragma unroll
            for (int q = 0; q < 4; q++) acc[i][j][q] = 0.f;

    auto loadTiles = [&](int st, int k0) {
        // A: [M,K] row-major, 16B chunks along k
        #pragma unroll
        for (int r = 0; r < (BM * (BK/4)) / NT; r++) {
            int i = tid + r * NT;
            int m = i >> 2;                 // BK/4 == 4 chunks per row
            int c = (i & 3) << 2;
            cp16(&As[st][m][c], &A[(size_t)(m0 + m) * lda + k0 + c]);
        }
        if (TB) {   // B: [N,K] row-major
            #pragma unroll
            for (int r = 0; r < (BN * (BK/4)) / NT; r++) {
                int i = tid + r * NT;
                int n = i >> 2;
                int c = (i & 3) << 2;
                int gn = n0 + n;
                if (GN) {
                    bool ok = gn < N;
                    cp16p(&Bs[st][n][c], ok ? &Bp[(size_t)gn * ldb + k0 + c] : (const float*)Bp, ok);
                } else {
                    cp16(&Bs[st][n][c], &Bp[(size_t)gn * ldb + k0 + c]);
                }
            }
        } else {    // B: [K,N] row-major, chunks along n
            #pragma unroll
            for (int r = 0; r < (BK * (BN/4)) / NT; r++) {
                int i = tid + r * NT;
                int kk = i / (BN/4);
                int c  = (i - kk * (BN/4)) << 2;
                cp16(&Bs[st][kk][c], &Bp[(size_t)(k0 + kk) * ldb + n0 + c]);
            }
        }
    };

    const int nk = K / BK;
    loadTiles(0, 0);
    CP_COMMIT();

    for (int kt = 0; kt < nk; kt++) {
        int cur = kt & 1;
        if (kt + 1 < nk) loadTiles(cur ^ 1, (kt + 1) * BK);
        CP_COMMIT();
        CP_WAIT1();
        __syncthreads();

        #pragma unroll
        for (int ks = 0; ks < 2; ks++) {
            uint32_t af[MI][4], bf[NI][2];
            #pragma unroll
            for (int i = 0; i < MI; i++) {
                int mr = wm * WM + i * 16 + g;
                af[i][0] = __float_as_uint(As[cur][mr    ][ks*8 + t4    ]);
                af[i][1] = __float_as_uint(As[cur][mr + 8][ks*8 + t4    ]);
                af[i][2] = __float_as_uint(As[cur][mr    ][ks*8 + t4 + 4]);
                af[i][3] = __float_as_uint(As[cur][mr + 8][ks*8 + t4 + 4]);
            }
            #pragma unroll
            for (int j = 0; j < NI; j++) {
                int nc = wn * WN + j * 8 + g;
                if (TB) {
                    bf[j][0] = __float_as_uint(Bs[cur][nc][ks*8 + t4    ]);
                    bf[j][1] = __float_as_uint(Bs[cur][nc][ks*8 + t4 + 4]);
                } else {
                    bf[j][0] = __float_as_uint(Bs[cur][ks*8 + t4    ][nc]);
                    bf[j][1] = __float_as_uint(Bs[cur][ks*8 + t4 + 4][nc]);
                }
            }
            #pragma unroll
            for (int i = 0; i < MI; i++)
                #pragma unroll
                for (int j = 0; j < NI; j++)
                    mma_tf32(acc[i][j], af[i][0], af[i][1], af[i][2], af[i][3],
                             bf[j][0], bf[j][1]);
        }
        __syncthreads();
    }

    // epilogue
    #pragma unroll
    for (int i = 0; i < MI; i++) {
        int r0 = m0 + wm * WM + i * 16 + g;
        #pragma unroll
        for (int j = 0; j < NI; j++) {
            int col = n0 + wn * WN + j * 8 + t4 * 2;
            if (GN && col >= N) continue;
            float b0v = 0.f, b1v = 0.f;
            if (bias) { b0v = bias[col]; b1v = bias[col + 1]; }
            float v0 = acc[i][j][0] * alpha + b0v;
            float v1 = acc[i][j][1] * alpha + b1v;
            float v2 = acc[i][j][2] * alpha + b0v;
            float v3 = acc[i][j][3] * alpha + b1v;
            if (RELU) {
                v0 = fmaxf(v0, 0.f); v1 = fmaxf(v1, 0.f);
                v2 = fmaxf(v2, 0.f); v3 = fmaxf(v3, 0.f);
            }
            if (TFO) {
                v0 = tf32r(v0); v1 = tf32r(v1); v2 = tf32r(v2); v3 = tf32r(v3);
            }
            *reinterpret_cast<float2*>(&C[(size_t)r0 * ldc + col])       = make_float2(v0, v1);
            *reinterpret_cast<float2*>(&C[(size_t)(r0 + 8) * ldc + col]) = make_float2(v2, v3);
        }
    }
}

// ---------------- softmax (rounds output for the AV GEMM) ----------------
__global__ void k_softmax(float* __restrict__ sc)
{
    long long row = blockIdx.x;
    float* r = sc + row * S;
    int t = threadIdx.x;
    float v0 = r[t], v1 = r[t + 256];
    __shared__ float red[256];
    red[t] = fmaxf(v0, v1); __syncthreads();
    for (int o = 128; o > 0; o >>= 1) { if (t < o) red[t] = fmaxf(red[t], red[t+o]); __syncthreads(); }
    float m = red[0]; __syncthreads();
    float e0 = expf(v0 - m), e1 = expf(v1 - m);
    red[t] = e0 + e1; __syncthreads();
    for (int o = 128; o > 0; o >>= 1) { if (t < o) red[t] += red[t+o]; __syncthreads(); }
    float inv = 1.f / red[0];
    r[t]       = tf32r(e0 * inv);
    r[t + 256] = tf32r(e1 * inv);
}

// ---------------- residual add + layernorm (writes exact + tf32 copies) ----------------
__global__ void k_add_ln(const float* __restrict__ xin, const float* __restrict__ res,
                         const float* __restrict__ g, const float* __restrict__ b,
                         float* __restrict__ xout, float* __restrict__ xtf)
{
    int row = blockIdx.x, t = threadIdx.x;
    long long base = (long long)row * D;
    float v0 = xin[base + t]       + res[base + t];
    float v1 = xin[base + t + 256] + res[base + t + 256];
    __shared__ float red[256];
    red[t] = v0 + v1; __syncthreads();
    for (int o = 128; o > 0; o >>= 1) { if (t < o) red[t] += red[t+o]; __syncthreads(); }
    float mean = red[0] * (1.f / D); __syncthreads();
    red[t] = v0*v0 + v1*v1; __syncthreads();
    for (int o = 128; o > 0; o >>= 1) { if (t < o) red[t] += red[t+o]; __syncthreads(); }
    float var = red[0] * (1.f / D) - mean*mean;
    float rs = rsqrtf(var + 1e-5f);
    float o0 = (v0 - mean) * rs * g[t]       + b[t];
    float o1 = (v1 - mean) * rs * g[t + 256] + b[t + 256];
    xout[base + t]       = o0;
    xout[base + t + 256] = o1;
    xtf [base + t]       = tf32r(o0);
    xtf [base + t + 256] = tf32r(o1);
}

// ---------------- embedding ----------------
__global__ void k_embed(const int* __restrict__ src, const float* __restrict__ emb,
                        const float* __restrict__ pos, float* __restrict__ x,
                        float* __restrict__ xtf)
{
    int idx = blockIdx.x * blockDim.x + threadIdx.x;
    int t = idx >> 9, d = idx & 511;
    float v = emb[(long long)src[t] * D + d] * SQRTD_F + pos[(t & 511) * D + d];
    x[idx]   = v;
    xtf[idx] = tf32r(v);
}

// ---------------- round static weights ----------------
__global__ void k_round_w(const float* __restrict__ opw, const float* __restrict__ ow, int nOw)
{
    int i = blockIdx.x * blockDim.x + threadIdx.x;
    if (i < L * D * D) d_wr[i] = tf32r(opw[i]);
    if (i < nOw)       d_owr[i] = tf32r(ow[i]);
}

// ---------------- batched prune pipeline ----------------
__device__ __forceinline__ const float* slot_w(int slot, const float* ipw,
                                               const float* w1, const float* w2, int& n)
{
    int t = slot / 6, l = slot - t * 6;
    if (t == 0) { n = 3 * D * D; return ipw + (size_t)l * 3 * D * D; }
    n = F * D;
    return (t == 1) ? w1 + (size_t)l * F * D : w2 + (size_t)l * F * D;
}

__global__ void k_zero_all()
{
    int i = blockIdx.x * blockDim.x + threadIdx.x;
    if (i < NSLOT * 2 * 65536) d_h2g[i] = 0;
    if (i < NSLOT * 4096)      d_h1g[i] = 0;
    if (i < NSLOT * 32)        d_h3g[i] = 0;
}

__global__ void k_etch_all(const float* __restrict__ ipw, const float* __restrict__ w1,
                           const float* __restrict__ w2)
{
    int slot = blockIdx.y;
    int n;
    const float* w = slot_w(slot, ipw, w1, w2, n);
    float inv = 1.f / (float)(n - 1);
    float* aout = d_abs_all + (size_t)slot * SLOT_STRIDE;
    unsigned* h1 = d_h1g + slot * 4096;

    __shared__ unsigned h[4096];
    for (int j = threadIdx.x; j < 4096; j += blockDim.x) h[j] = 0;
    __syncthreads();
    int stride = gridDim.x * blockDim.x;
    for (int i = blockIdx.x * blockDim.x + threadIdx.x; i < n; i += stride) {
        float wv = w[i];
        float b0 = sinf(wv * PI_F);
        b0 = fminf(fmaxf(b0, -1.f), 1.f);
        float bl = b0 + b0 * cosf((float)i * inv + THIRD_F) * 1.5f;
        float e = cosf(bl * PI2_F) + bl * bl * DEVPI_F;
        float a = fabsf(e);
        aout[i] = a;
        atomicAdd(&h[__float_as_uint(a) >> 20], 1u);
    }
    __syncthreads();
    for (int j = threadIdx.x; j < 4096; j += blockDim.x) {
        unsigned c = h[j];
        if (c) atomicAdd(&h1[j], c);
    }
}

__global__ void k_scan1_all(const float* ipw, const float* w1, const float* w2)
{
    int slot = blockIdx.x;
    int n; slot_w(slot, ipw, w1, w2, n);
    unsigned rA = (unsigned)((n - 1) >> 2);
    unsigned rB = rA + 1;
    const unsigned* h1 = d_h1g + slot * 4096;
    unsigned* sel = d_selg + slot * 8;

    __shared__ unsigned part[256];
    __shared__ unsigned pref[256];
    int t = threadIdx.x, base = t * 16;
    unsigned c[16]; unsigned s = 0;
    for (int j = 0; j < 16; j++) { c[j] = h1[base + j]; s += c[j]; }
    part[t] = s; __syncthreads();
    if (t == 0) { unsigned a = 0; for (int i = 0; i < 256; i++) { pref[i] = a; a += part[i]; } }
    __syncthreads();
    unsigned p = pref[t];
    for (int j = 0; j < 16; j++) {
        if (rA >= p && rA < p + c[j]) { sel[0] = base + j; sel[1] = rA - p; }
        if (rB >= p && rB < p + c[j]) { sel[2] = base + j; sel[3] = rB - p; }
        p += c[j];
    }
}

__global__ void k_hist2_all(const float* ipw, const float* w1, const float* w2)
{
    int slot = blockIdx.y;
    int n; slot_w(slot, ipw, w1, w2, n);
    const float* ab = d_abs_all + (size_t)slot * SLOT_STRIDE;
    const unsigned* sel = d_selg + slot * 8;
    unsigned* h2 = d_h2g + (size_t)slot * 131072;
    unsigned sA = sel[0], sB = sel[2];
    int stride = gridDim.x * blockDim.x;
    for (int i = blockIdx.x * blockDim.x + threadIdx.x; i < n; i += stride) {
        unsigned u = __float_as_uint(ab[i]);
        unsigned hi = u >> 20, mid = (u >> 4) & 0xFFFFu;
        if (hi == sA) atomicAdd(&h2[mid], 1u);
        if (hi == sB) atomicAdd(&h2[65536 + mid], 1u);
    }
}

__global__ void k_scan2_all()
{
    int slot = blockIdx.x;
    unsigned* sel = d_selg + slot * 8;
    __shared__ unsigned part[256];
    __shared__ unsigned pref[256];
    int t = threadIdx.x;
    for (int sidx = 0; sidx < 2; sidx++) {
        unsigned rank = sel[1 + sidx * 2];
        const unsigned* hb = d_h2g + (size_t)slot * 131072 + sidx * 65536;
        int base = t * 256;
        unsigned s = 0;
        for (int j = 0; j < 256; j++) s += hb[base + j];
        part[t] = s; __syncthreads();
        if (t == 0) { unsigned a = 0; for (int i = 0; i < 256; i++) { pref[i] = a; a += part[i]; } }
        __syncthreads();
        unsigned p = pref[t];
        for (int j = 0; j < 256; j++) {
            unsigned c = hb[base + j];
            if (rank >= p && rank < p + c) { sel[4 + sidx*2] = base + j; sel[5 + sidx*2] = rank - p; }
            p += c;
        }
        __syncthreads();
    }
}

__global__ void k_hist3_all(const float* ipw, const float* w1, const float* w2)
{
    int slot = blockIdx.y;
    int n; slot_w(slot, ipw, w1, w2, n);
    const float* ab = d_abs_all + (size_t)slot * SLOT_STRIDE;
    const unsigned* sel = d_selg + slot * 8;
    unsigned* h3 = d_h3g + slot * 32;
    unsigned kA = (sel[0] << 16) | sel[4];
    unsigned kB = (sel[2] << 16) | sel[6];
    int stride = gridDim.x * blockDim.x;
    for (int i = blockIdx.x * blockDim.x + threadIdx.x; i < n; i += stride) {
        unsigned u = __float_as_uint(ab[i]);
        unsigned top = u >> 4;
        if (top == kA) atomicAdd(&h3[u & 15u], 1u);
        if (top == kB) atomicAdd(&h3[16 + (u & 15u)], 1u);
    }
}

__global__ void k_thr_all(const float* ipw, const float* w1, const float* w2)
{
    int slot = blockIdx.x * blockDim.x + threadIdx.x;
    if (slot >= NSLOT) return;
    int n; slot_w(slot, ipw, w1, w2, n);
    float frac = 0.25f * (float)((n - 1) & 3);
    const unsigned* sel = d_selg + slot * 8;
    const unsigned* h3 = d_h3g + slot * 32;
    unsigned remA = sel[5]; unsigned lowA = 0;
    for (int j = 0; j < 16; j++) { unsigned c = h3[j]; if (remA < c) { lowA = j; break; } remA -= c; }
    unsigned remB = sel[7]; unsigned lowB = 0;
    for (int j = 0; j < 16; j++) { unsigned c = h3[16 + j]; if (remB < c) { lowB = j; break; } remB -= c; }
    float vA = __uint_as_float((sel[0] << 20) | (sel[4] << 4) | lowA);
    float vB = __uint_as_float((sel[2] << 20) | (sel[6] << 4) | lowB);
    d_thrg[slot] = vA + frac * (vB - vA);
}

// masks AND tf32-rounds the surviving weights (they only feed GEMMs)
__global__ void k_mask_all(const float* __restrict__ ipw, const float* __restrict__ w1,
                           const float* __restrict__ w2)
{
    int slot = blockIdx.y;
    int n;
    const float* w = slot_w(slot, ipw, w1, w2, n);
    int i = blockIdx.x * blockDim.x + threadIdx.x;
    if (i >= n) return;
    float thr = d_thrg[slot];
    d_wp[(size_t)slot * SLOT_STRIDE + i] =
        (d_abs_all[(size_t)slot * SLOT_STRIDE + i] > thr) ? tf32r(w[i]) : 0.f;
}

// ---------------- entry point ----------------
extern "C" void kernel_launch(void* const* d_in, const int* in_sizes, int n_in,
                              void* d_out, int out_size)
{
    const int*   src = (const int*)  d_in[0];
    const float* emb = (const float*)d_in[1];
    const float* pos = (const float*)d_in[2];
    const float* ipw = (const float*)d_in[3];
    const float* ipb = (const float*)d_in[4];
    const float* opw = (const float*)d_in[5];
    const float* opb = (const float*)d_in[6];
    const float* l1g = (const float*)d_in[7];
    const float* l1b = (const float*)d_in[8];
    const float* l2g = (const float*)d_in[9];
    const float* l2b = (const float*)d_in[10];
    const float* w1  = (const float*)d_in[11];
    const float* b1  = (const float*)d_in[12];
    const float* w2  = (const float*)d_in[13];
    const float* b2  = (const float*)d_in[14];
    const float* ow  = (const float*)d_in[15];
    const float* ob  = (const float*)d_in[16];
    const int V = in_sizes[16];
    float* out = (float*)d_out;

    float *px, *pxtf, *pqkv, *psc, *pao, *pff, *ptmp, *pwp, *pwr, *powr;
    cudaGetSymbolAddress((void**)&px,   d_x);
    cudaGetSymbolAddress((void**)&pxtf, d_xtf);
    cudaGetSymbolAddress((void**)&pqkv, d_qkv);
    cudaGetSymbolAddress((void**)&psc,  d_sc);
    cudaGetSymbolAddress((void**)&pao,  d_ao);
    cudaGetSymbolAddress((void**)&pff,  d_ff);
    cudaGetSymbolAddress((void**)&ptmp, d_tmp);
    cudaGetSymbolAddress((void**)&pwp,  d_wp);
    cudaGetSymbolAddress((void**)&pwr,  d_wr);
    cudaGetSymbolAddress((void**)&powr, d_owr);

    k_embed<<<MT * D / 256, 256>>>(src, emb, pos, px, pxtf);
    k_round_w<<<(V * D + 255) / 256, 256>>>(opw, ow, V * D);

    // prune all 18 weight matrices up-front
    k_zero_all<<<(NSLOT * 2 * 65536 + 255) / 256, 256>>>();
    k_etch_all <<<dim3(128, NSLOT), 256>>>(ipw, w1, w2);
    k_scan1_all<<<NSLOT, 256>>>(ipw, w1, w2);
    k_hist2_all<<<dim3(128, NSLOT), 256>>>(ipw, w1, w2);
    k_scan2_all<<<NSLOT, 256>>>();
    k_hist3_all<<<dim3(128, NSLOT), 256>>>(ipw, w1, w2);
    k_thr_all  <<<1, 32>>>(ipw, w1, w2);
    k_mask_all <<<dim3(4096, NSLOT), 256>>>(ipw, w1, w2);

    for (int l = 0; l < L; l++) {
        const float* wi_l = pwp + (size_t)(0 * 6 + l) * SLOT_STRIDE;
        const float* w1_l = pwp + (size_t)(1 * 6 + l) * SLOT_STRIDE;
        const float* w2_l = pwp + (size_t)(2 * 6 + l) * SLOT_STRIDE;

        // qkv = x @ wi^T + b  (output rounded: feeds attention GEMMs)
        k_mma<128,128,2,2,true,false,false,true><<<dim3((3*D)/128, MT/128, 1), 128>>>(
            MT, 3*D, D, pxtf, D, 0, 0, wi_l, D, 0, 0, pqkv, 3*D, 0, 0, 1,
            ipb + (size_t)l * 3 * D, 1.f);
        // scores = Q K^T / 8
        k_mma<128,128,2,2,true,false,false,false><<<dim3(S/128, S/128, BH), 128>>>(
            S, S, DH,
            pqkv,     3*D, (long long)S*3*D, DH,
            pqkv + D, 3*D, (long long)S*3*D, DH,
            psc, S, (long long)H*S*S, (long long)S*S,
            H, nullptr, 0.125f);
        k_softmax<<<BH * S, 256>>>(psc);
        // o = att @ V  (output rounded: feeds out_proj GEMM)
        k_mma<128,64,2,2,false,false,false,true><<<dim3(1, S/128, BH), 128>>>(
            S, DH, S,
            psc, S, (long long)H*S*S, (long long)S*S,
            pqkv + 2*D, 3*D, (long long)S*3*D, DH,
            pao, D, (long long)S*D, DH,
            H, nullptr, 1.f);
        // out projection (exact output: feeds residual)
        k_mma<128,128,2,2,true,false,false,false><<<dim3(D/128, MT/128, 1), 128>>>(
            MT, D, D, pao, D, 0, 0, pwr + (size_t)l*D*D, D, 0, 0,
            ptmp, D, 0, 0, 1, opb + (size_t)l*D, 1.f);
        k_add_ln<<<MT, 256>>>(px, ptmp, l1g + (size_t)l*D, l1b + (size_t)l*D, px, pxtf);

        // feed-forward
        k_mma<128,128,2,2,true,true,false,true><<<dim3(F/128, MT/128, 1), 128>>>(
            MT, F, D, pxtf, D, 0, 0, w1_l, D, 0, 0, pff, F, 0, 0, 1,
            b1 + (size_t)l*F, 1.f);
        k_mma<128,128,2,2,true,false,false,false><<<dim3(D/128, MT/128, 1), 128>>>(
            MT, D, F, pff, F, 0, 0, w2_l, F, 0, 0, ptmp, D, 0, 0, 1,
            b2 + (size_t)l*D, 1.f);
        k_add_ln<<<MT, 256>>>(px, ptmp, l2g + (size_t)l*D, l2b + (size_t)l*D, px, pxtf);
    }

    // logits
    k_mma<128,128,2,2,true,false,true,false><<<dim3((V + 127) / 128, MT / 128, 1), 128>>>(
        MT, V, D, pxtf, D, 0, 0, powr, D, 0, 0, out, V, 0, 0, 1, ob, 1.f);
}

// round 5
// speedup vs baseline: 5.1305x; 1.3881x over previous
#include <cuda_runtime.h>
#include <cstdint>
#include <math.h>

// ---------------- constants ----------------
#define PI_F      3.14159265358979323846f
#define PI2_F     9.86960440108935861883f
#define THIRD_F   2.09439510239319549231f
#define DEVPI_F   0.003183098861837907f
#define SQRTD_F   22.62741699796952f

constexpr int S  = 512;
constexpr int D  = 512;
constexpr int H  = 8;
constexpr int DH = 64;
constexpr int L  = 6;
constexpr int F  = 2048;
constexpr int BB = 16;
constexpr int MT = BB * S;   // 8192 tokens
constexpr int BH = BB * H;   // 128
constexpr int NSLOT = 18;
constexpr size_t SLOT_STRIDE = 1048576;
constexpr int VMAX = 10240;

// Feature gate: tcgen05 only exists on arch-specific (sm_103a) / family (sm_103f) targets.
#if !defined(__CUDA_ARCH__) || defined(__CUDA_ARCH_FEAT_SM103_ALL) || defined(__CUDA_ARCH_SPECIFIC__) || defined(__CUDA_ARCH_FAMILY_SPECIFIC__)
#define TC_AVAIL 1
#else
#define TC_AVAIL 0
#endif

// ---------------- device scratch ----------------
__device__ __align__(128) float d_x   [MT * D];
__device__ __align__(128) float d_xtf [MT * D];
__device__ __align__(128) float d_qkv [MT * 3 * D];
__device__ __align__(128) float d_sc  [(size_t)BH * S * S];
__device__ __align__(128) float d_ao  [MT * D];
__device__ __align__(128) float d_ff  [MT * F];
__device__ __align__(128) float d_tmp [MT * D];
__device__ __align__(128) float d_wp  [NSLOT * SLOT_STRIDE];
__device__ __align__(128) float d_wr  [L * D * D];
__device__ __align__(128) float d_owr [VMAX * D];
__device__ __align__(128) float d_abs_all[NSLOT * SLOT_STRIDE];
__device__ unsigned d_h1g[NSLOT * 4096];
__device__ unsigned d_h2g[NSLOT * 2 * 65536];
__device__ unsigned d_h3g[NSLOT * 32];
__device__ unsigned d_selg[NSLOT * 8];
__device__ float d_thrg[NSLOT];

// ---------------- helpers ----------------
__device__ __forceinline__ float tf32r(float f) {
    uint32_t u;
    asm("cvt.rna.tf32.f32 %0, %1;" : "=r"(u) : "f"(f));
    return __uint_as_float(u);
}

__device__ __forceinline__ void mma_tf32(float c[4],
    uint32_t a0, uint32_t a1, uint32_t a2, uint32_t a3,
    uint32_t b0, uint32_t b1)
{
    asm volatile(
        "mma.sync.aligned.m16n8k8.row.col.f32.tf32.tf32.f32 "
        "{%0,%1,%2,%3}, {%4,%5,%6,%7}, {%8,%9}, {%0,%1,%2,%3};"
        : "+f"(c[0]), "+f"(c[1]), "+f"(c[2]), "+f"(c[3])
        : "r"(a0), "r"(a1), "r"(a2), "r"(a3), "r"(b0), "r"(b1));
}

__device__ __forceinline__ void cp16(void* d, const void* s) {
    uint32_t a = (uint32_t)__cvta_generic_to_shared(d);
    asm volatile("cp.async.cg.shared.global [%0], [%1], 16;" :: "r"(a), "l"(s));
}
__device__ __forceinline__ void cp16p(void* d, const void* s, bool p) {
    uint32_t a = (uint32_t)__cvta_generic_to_shared(d);
    int sz = p ? 16 : 0;
    asm volatile("cp.async.cg.shared.global [%0], [%1], 16, %2;" :: "r"(a), "l"(s), "r"(sz));
}
#define CP_COMMIT() asm volatile("cp.async.commit_group;")
#define CP_WAIT1()  asm volatile("cp.async.wait_group 1;")
#define CP_WAIT2()  asm volatile("cp.async.wait_group 2;")

// ================= tcgen05 tf32 GEMM (guarded) =================
constexpr int TC_BM = 128, TC_BN = 256, TC_BK = 32, TC_NS = 3;
constexpr int TC_ASZ = TC_BM * TC_BK * 4;       // 16384 (128 rows x 128B)
constexpr int TC_BSZ = TC_BN * TC_BK * 4;       // 32768 (256 rows x 128B)
constexpr int TC_SMEM = 1024 + TC_NS * (TC_ASZ + TC_BSZ);   // 148480

#if TC_AVAIL
__device__ __forceinline__ uint32_t elect1() {
    uint32_t pred;
    asm volatile("{\n\t.reg .pred p;\n\telect.sync _|p, 0xFFFFFFFF;\n\t"
                 "selp.b32 %0, 1, 0, p;\n\t}" : "=r"(pred));
    return pred;
}
#define MBAR_INIT(addr, cnt) \
    asm volatile("mbarrier.init.shared.b64 [%0], %1;" :: "r"(addr), "r"(cnt) : "memory")
#define MBAR_WAIT(addr, par) do { \
    asm volatile("{\n\t.reg .pred P1;\n\tWL%=:\n\t" \
        "mbarrier.try_wait.parity.acquire.cta.shared::cta.b64 P1, [%0], %1, 0x989680;\n\t" \
        "@P1 bra.uni WD%=;\n\tbra.uni WL%=;\n\tWD%=:\n\t}" \
        :: "r"(addr), "r"(par) : "memory"); \
} while (0)
#define TC_ALLOC(sm, n)   asm volatile("tcgen05.alloc.cta_group::1.sync.aligned.shared::cta.b32 [%0], %1;" :: "r"(sm), "r"(n) : "memory")
#define TC_DEALLOC(t, n)  asm volatile("tcgen05.dealloc.cta_group::1.sync.aligned.b32 %0, %1;" :: "r"(t), "r"(n))
#define TC_COMMIT(mb)     asm volatile("tcgen05.commit.cta_group::1.mbarrier::arrive::one.shared::cluster.b64 [%0];" :: "r"(mb) : "memory")
#define TC_FENCE_AFTER()  asm volatile("tcgen05.fence::after_thread_sync;" ::: "memory")
#define TC_FENCE_BEFORE() asm volatile("tcgen05.fence::before_thread_sync;" ::: "memory")
#define TC_WAIT_LD()      asm volatile("tcgen05.wait::ld.sync.aligned;" ::: "memory")
#define FENCE_PROXY()     asm volatile("fence.proxy.async.shared::cta;" ::: "memory")

#define TC_LD_X32(r, addr) \
    asm volatile("tcgen05.ld.sync.aligned.32x32b.x32.b32 " \
        "{%0, %1, %2, %3, %4, %5, %6, %7, %8, %9, %10, %11, %12, %13, %14, %15, " \
        " %16, %17, %18, %19, %20, %21, %22, %23, %24, %25, %26, %27, %28, %29, %30, %31}, [%32];" \
        : "=r"((r)[0]),  "=r"((r)[1]),  "=r"((r)[2]),  "=r"((r)[3]), \
          "=r"((r)[4]),  "=r"((r)[5]),  "=r"((r)[6]),  "=r"((r)[7]), \
          "=r"((r)[8]),  "=r"((r)[9]),  "=r"((r)[10]), "=r"((r)[11]), \
          "=r"((r)[12]), "=r"((r)[13]), "=r"((r)[14]), "=r"((r)[15]), \
          "=r"((r)[16]), "=r"((r)[17]), "=r"((r)[18]), "=r"((r)[19]), \
          "=r"((r)[20]), "=r"((r)[21]), "=r"((r)[22]), "=r"((r)[23]), \
          "=r"((r)[24]), "=r"((r)[25]), "=r"((r)[26]), "=r"((r)[27]), \
          "=r"((r)[28]), "=r"((r)[29]), "=r"((r)[30]), "=r"((r)[31]) \
        : "r"(addr))

static constexpr uint64_t SMEM_DESC_BASE =
    (uint64_t(2) << 61) | (uint64_t(1) << 46) | (uint64_t(64) << 32) | (uint64_t(1) << 16);
#define MK_DESC(a) (SMEM_DESC_BASE | ((uint64_t)((a) >> 4) & 0x3FFF))

__device__ __forceinline__ void mma_tc(uint32_t d, uint64_t ad, uint64_t bd,
                                       uint32_t idesc, bool en)
{
    uint32_t e = en ? 1 : 0;
    asm volatile(
        "{\n\t.reg .pred p;\n\tsetp.ne.u32 p, %4, 0;\n\t"
        "tcgen05.mma.cta_group::1.kind::tf32 [%0], %1, %2, %3, {%5,%5,%5,%5}, p;\n\t}"
        :: "r"(d), "l"(ad), "l"(bd), "r"(idesc), "r"(e), "r"(0u) : "memory");
}
#endif  // TC_AVAIL

constexpr uint32_t TC_IDESC =
    (1u << 4) | (2u << 7) | (2u << 10) | ((TC_BN / 8) << 17) | ((TC_BM / 16) << 24);

// C[m,n] = sum_k A[m,k]*B[n,k] + bias[n]; operands pre-rounded to tf32 values.
template<bool RELU, bool GN, bool TFO>
__global__ void __launch_bounds__(256, 1)
k_tc(int N, int K,
     const float* __restrict__ A, int lda,
     const float* __restrict__ B, int ldb,
     float* __restrict__ C, int ldc,
     const float* __restrict__ bias)
{
#if TC_AVAIL
    extern __shared__ char smem[];
    uint32_t sbase = (uint32_t)__cvta_generic_to_shared(smem);
    const int tid = threadIdx.x, lane = tid & 31, warp = tid >> 5;
    const int m0 = blockIdx.y * TC_BM, n0 = blockIdx.x * TC_BN;

    if (warp == 0) TC_ALLOC(sbase, 256);
    if (tid == 0) {
        #pragma unroll
        for (int s = 0; s < TC_NS; s++) MBAR_INIT(sbase + 16 + 8 * s, 1);
    }
    __syncthreads();
    uint32_t tmem;
    asm volatile("ld.shared.b32 %0, [%1];" : "=r"(tmem) : "r"(sbase));

    const uint32_t aoff = 1024, boff = 1024 + TC_NS * TC_ASZ;

    auto loadStage = [&](int st, int k0) {
        char* pa = smem + aoff + st * TC_ASZ;
        char* pb = smem + boff + st * TC_BSZ;
        // A: 128 rows x 8 chunks(16B) = 1024 -> 4 per thread
        #pragma unroll
        for (int r = 0; r < 4; r++) {
            int i = tid + r * 256;
            int m = i >> 3, c = i & 7;
            int cs = c ^ (m & 7);     // SW128
            cp16(pa + m * 128 + cs * 16, &A[(size_t)(m0 + m) * lda + k0 + c * 4]);
        }
        // B: 256 rows x 8 chunks = 2048 -> 8 per thread
        #pragma unroll
        for (int r = 0; r < 8; r++) {
            int i = tid + r * 256;
            int n = i >> 3, c = i & 7;
            int cs = c ^ (n & 7);
            int gn = n0 + n;
            if (GN) {
                bool ok = gn < N;
                cp16p(pb + n * 128 + cs * 16,
                      ok ? &B[(size_t)gn * ldb + k0 + c * 4] : (const float*)B, ok);
            } else {
                cp16(pb + n * 128 + cs * 16, &B[(size_t)gn * ldb + k0 + c * 4]);
            }
        }
    };

    const int nk = K / TC_BK;

    #pragma unroll
    for (int s = 0; s < TC_NS; s++) { loadStage(s, s * TC_BK); CP_COMMIT(); }

    for (int kt = 0; kt < nk; kt++) {
        int cur = kt % TC_NS;
        CP_WAIT2();
        __syncthreads();
        FENCE_PROXY();
        if (warp == 0 && elect1()) {
            uint64_t ad = MK_DESC(sbase + aoff + cur * TC_ASZ);
            uint64_t bd = MK_DESC(sbase + boff + cur * TC_BSZ);
            #pragma unroll
            for (int j = 0; j < 4; j++)
                mma_tc(tmem, ad + j * 2, bd + j * 2, TC_IDESC, (kt > 0) || (j > 0));
            TC_COMMIT(sbase + 16 + 8 * cur);
        }
        MBAR_WAIT(sbase + 16 + 8 * cur, (kt / TC_NS) & 1);
        int kn = kt + TC_NS;
        if (kn < nk) loadStage(cur, kn * TC_BK);
        CP_COMMIT();
    }

    __syncthreads();
    TC_FENCE_AFTER();

    // epilogue: warp w reads its subpartition (rows (w&3)*32..); cols split by w>>2
    float* myep = (float*)(smem + 1024) + warp * (32 * 33);
    int rbase = m0 + (warp & 3) * 32;
    int cbase = (warp >> 2) * 128;

    #pragma unroll
    for (int ch = 0; ch < 4; ch++) {
        int c0 = cbase + ch * 32;
        uint32_t regs[32];
        TC_LD_X32(regs, tmem + c0);
        TC_WAIT_LD();
        #pragma unroll
        for (int c = 0; c < 32; c++) {
            float v = __uint_as_float(regs[c]);
            if (!GN || (n0 + c0 + c) < N) {
                v += bias[n0 + c0 + c];
                if (RELU) v = fmaxf(v, 0.f);
                if (TFO)  v = tf32r(v);
            }
            myep[lane * 33 + c] = v;
        }
        __syncwarp();
        int col = n0 + c0 + lane;
        #pragma unroll
        for (int i = 0; i < 32; i++) {
            if (!GN || col < N)
                C[(size_t)(rbase + i) * ldc + col] = myep[i * 33 + lane];
        }
        __syncwarp();
    }

    __syncthreads();
    if (warp == 0) { TC_FENCE_BEFORE(); TC_DEALLOC(tmem, 256); }
#endif  // TC_AVAIL (else: empty stub — host detects via numRegs and falls back)
}

// ================= mma.sync GEMM (R3, full-featured) =================
template<int BM,int BN,int WARPS_M,int WARPS_N,bool TB,bool RELU,bool GN,bool TFO>
__global__ void __launch_bounds__(WARPS_M*WARPS_N*32)
k_mma(int M, int N, int K,
      const float* __restrict__ Ag, int lda, long long sA1, long long sA2,
      const float* __restrict__ Bg, int ldb, long long sB1, long long sB2,
      float* __restrict__ Cg, int ldc, long long sC1, long long sC2,
      int zdiv, const float* __restrict__ bias, float alpha)
{
    constexpr int BK = 16;
    constexpr int NT = WARPS_M * WARPS_N * 32;
    constexpr int WM = BM / WARPS_M, WN = BN / WARPS_N;
    constexpr int MI = WM / 16, NI = WN / 8;
    constexpr int AST = BK + 4;
    constexpr int BROWS = TB ? BN : BK;
    constexpr int BCOLS = TB ? (BK + 4) : (BN + 8);

    __shared__ __align__(16) float As[2][BM][AST];
    __shared__ __align__(16) float Bs[2][BROWS][BCOLS];

    const int bz = blockIdx.z;
    const int z1 = bz / zdiv, z2 = bz - z1 * zdiv;
    const float* A  = Ag + z1 * sA1 + z2 * sA2;
    const float* Bp = Bg + z1 * sB1 + z2 * sB2;
    float* C        = Cg + z1 * sC1 + z2 * sC2;

    const int m0 = blockIdx.y * BM, n0 = blockIdx.x * BN;
    const int tid  = threadIdx.x;
    const int lane = tid & 31, warp = tid >> 5;
    const int wm = warp / WARPS_N, wn = warp - wm * WARPS_N;
    const int g = lane >> 2, t4 = lane & 3;

    float acc[MI][NI][4];
    #pragma unroll
    for (int i = 0; i < MI; i++)
        #pragma unroll
        for (int j = 0; j < NI; j++)
            #pragma unroll
            for (int q = 0; q < 4; q++) acc[i][j][q] = 0.f;

    auto loadTiles = [&](int st, int k0) {
        #pragma unroll
        for (int r = 0; r < (BM * (BK/4)) / NT; r++) {
            int i = tid + r * NT;
            int m = i >> 2;
            int c = (i & 3) << 2;
            cp16(&As[st][m][c], &A[(size_t)(m0 + m) * lda + k0 + c]);
        }
        if (TB) {
            #pragma unroll
            for (int r = 0; r < (BN * (BK/4)) / NT; r++) {
                int i = tid + r * NT;
                int n = i >> 2;
                int c = (i & 3) << 2;
                int gn = n0 + n;
                if (GN) {
                    bool ok = gn < N;
                    cp16p(&Bs[st][n][c], ok ? &Bp[(size_t)gn * ldb + k0 + c] : (const float*)Bp, ok);
                } else {
                    cp16(&Bs[st][n][c], &Bp[(size_t)gn * ldb + k0 + c]);
                }
            }
        } else {
            #pragma unroll
            for (int r = 0; r < (BK * (BN/4)) / NT; r++) {
                int i = tid + r * NT;
                int kk = i / (BN/4);
                int c  = (i - kk * (BN/4)) << 2;
                cp16(&Bs[st][kk][c], &Bp[(size_t)(k0 + kk) * ldb + n0 + c]);
            }
        }
    };

    const int nk = K / BK;
    loadTiles(0, 0);
    CP_COMMIT();

    for (int kt = 0; kt < nk; kt++) {
        int cur = kt & 1;
        if (kt + 1 < nk) loadTiles(cur ^ 1, (kt + 1) * BK);
        CP_COMMIT();
        CP_WAIT1();
        __syncthreads();

        #pragma unroll
        for (int ks = 0; ks < 2; ks++) {
            uint32_t af[MI][4], bf[NI][2];
            #pragma unroll
            for (int i = 0; i < MI; i++) {
                int mr = wm * WM + i * 16 + g;
                af[i][0] = __float_as_uint(As[cur][mr    ][ks*8 + t4    ]);
                af[i][1] = __float_as_uint(As[cur][mr + 8][ks*8 + t4    ]);
                af[i][2] = __float_as_uint(As[cur][mr    ][ks*8 + t4 + 4]);
                af[i][3] = __float_as_uint(As[cur][mr + 8][ks*8 + t4 + 4]);
            }
            #pragma unroll
            for (int j = 0; j < NI; j++) {
                int nc = wn * WN + j * 8 + g;
                if (TB) {
                    bf[j][0] = __float_as_uint(Bs[cur][nc][ks*8 + t4    ]);
                    bf[j][1] = __float_as_uint(Bs[cur][nc][ks*8 + t4 + 4]);
                } else {
                    bf[j][0] = __float_as_uint(Bs[cur][ks*8 + t4    ][nc]);
                    bf[j][1] = __float_as_uint(Bs[cur][ks*8 + t4 + 4][nc]);
                }
            }
            #pragma unroll
            for (int i = 0; i < MI; i++)
                #pragma unroll
                for (int j = 0; j < NI; j++)
                    mma_tf32(acc[i][j], af[i][0], af[i][1], af[i][2], af[i][3],
                             bf[j][0], bf[j][1]);
        }
        __syncthreads();
    }

    #pragma unroll
    for (int i = 0; i < MI; i++) {
        int r0 = m0 + wm * WM + i * 16 + g;
        #pragma unroll
        for (int j = 0; j < NI; j++) {
            int col = n0 + wn * WN + j * 8 + t4 * 2;
            if (GN && col >= N) continue;
            float b0v = 0.f, b1v = 0.f;
            if (bias) { b0v = bias[col]; b1v = bias[col + 1]; }
            float v0 = acc[i][j][0] * alpha + b0v;
            float v1 = acc[i][j][1] * alpha + b1v;
            float v2 = acc[i][j][2] * alpha + b0v;
            float v3 = acc[i][j][3] * alpha + b1v;
            if (RELU) {
                v0 = fmaxf(v0, 0.f); v1 = fmaxf(v1, 0.f);
                v2 = fmaxf(v2, 0.f); v3 = fmaxf(v3, 0.f);
            }
            if (TFO) {
                v0 = tf32r(v0); v1 = tf32r(v1); v2 = tf32r(v2); v3 = tf32r(v3);
            }
            *reinterpret_cast<float2*>(&C[(size_t)r0 * ldc + col])       = make_float2(v0, v1);
            *reinterpret_cast<float2*>(&C[(size_t)(r0 + 8) * ldc + col]) = make_float2(v2, v3);
        }
    }
}

// ---------------- softmax ----------------
__global__ void k_softmax(float* __restrict__ sc)
{
    long long row = blockIdx.x;
    float* r = sc + row * S;
    int t = threadIdx.x;
    float v0 = r[t], v1 = r[t + 256];
    __shared__ float red[256];
    red[t] = fmaxf(v0, v1); __syncthreads();
    for (int o = 128; o > 0; o >>= 1) { if (t < o) red[t] = fmaxf(red[t], red[t+o]); __syncthreads(); }
    float m = red[0]; __syncthreads();
    float e0 = expf(v0 - m), e1 = expf(v1 - m);
    red[t] = e0 + e1; __syncthreads();
    for (int o = 128; o > 0; o >>= 1) { if (t < o) red[t] += red[t+o]; __syncthreads(); }
    float inv = 1.f / red[0];
    r[t]       = tf32r(e0 * inv);
    r[t + 256] = tf32r(e1 * inv);
}

// ---------------- residual add + layernorm ----------------
__global__ void k_add_ln(const float* __restrict__ xin, const float* __restrict__ res,
                         const float* __restrict__ g, const float* __restrict__ b,
                         float* __restrict__ xout, float* __restrict__ xtf)
{
    int row = blockIdx.x, t = threadIdx.x;
    long long base = (long long)row * D;
    float v0 = xin[base + t]       + res[base + t];
    float v1 = xin[base + t + 256] + res[base + t + 256];
    __shared__ float red[256];
    red[t] = v0 + v1; __syncthreads();
    for (int o = 128; o > 0; o >>= 1) { if (t < o) red[t] += red[t+o]; __syncthreads(); }
    float mean = red[0] * (1.f / D); __syncthreads();
    red[t] = v0*v0 + v1*v1; __syncthreads();
    for (int o = 128; o > 0; o >>= 1) { if (t < o) red[t] += red[t+o]; __syncthreads(); }
    float var = red[0] * (1.f / D) - mean*mean;
    float rs = rsqrtf(var + 1e-5f);
    float o0 = (v0 - mean) * rs * g[t]       + b[t];
    float o1 = (v1 - mean) * rs * g[t + 256] + b[t + 256];
    xout[base + t]       = o0;
    xout[base + t + 256] = o1;
    xtf [base + t]       = tf32r(o0);
    xtf [base + t + 256] = tf32r(o1);
}

// ---------------- embedding ----------------
__global__ void k_embed(const int* __restrict__ src, const float* __restrict__ emb,
                        const float* __restrict__ pos, float* __restrict__ x,
                        float* __restrict__ xtf)
{
    int idx = blockIdx.x * blockDim.x + threadIdx.x;
    int t = idx >> 9, d = idx & 511;
    float v = emb[(long long)src[t] * D + d] * SQRTD_F + pos[(t & 511) * D + d];
    x[idx]   = v;
    xtf[idx] = tf32r(v);
}

// ---------------- round static weights ----------------
__global__ void k_round_w(const float* __restrict__ opw, const float* __restrict__ ow, int nOw)
{
    int i = blockIdx.x * blockDim.x + threadIdx.x;
    if (i < L * D * D) d_wr[i] = tf32r(opw[i]);
    if (i < nOw)       d_owr[i] = tf32r(ow[i]);
}

// ---------------- batched prune pipeline ----------------
__device__ __forceinline__ const float* slot_w(int slot, const float* ipw,
                                               const float* w1, const float* w2, int& n)
{
    int t = slot / 6, l = slot - t * 6;
    if (t == 0) { n = 3 * D * D; return ipw + (size_t)l * 3 * D * D; }
    n = F * D;
    return (t == 1) ? w1 + (size_t)l * F * D : w2 + (size_t)l * F * D;
}

__global__ void k_zero_all()
{
    int i = blockIdx.x * blockDim.x + threadIdx.x;
    if (i < NSLOT * 2 * 65536) d_h2g[i] = 0;
    if (i < NSLOT * 4096)      d_h1g[i] = 0;
    if (i < NSLOT * 32)        d_h3g[i] = 0;
}

__global__ void k_etch_all(const float* __restrict__ ipw, const float* __restrict__ w1,
                           const float* __restrict__ w2)
{
    int slot = blockIdx.y;
    int n;
    const float* w = slot_w(slot, ipw, w1, w2, n);
    float inv = 1.f / (float)(n - 1);
    float* aout = d_abs_all + (size_t)slot * SLOT_STRIDE;
    unsigned* h1 = d_h1g + slot * 4096;

    __shared__ unsigned h[4096];
    for (int j = threadIdx.x; j < 4096; j += blockDim.x) h[j] = 0;
    __syncthreads();
    int stride = gridDim.x * blockDim.x;
    for (int i = blockIdx.x * blockDim.x + threadIdx.x; i < n; i += stride) {
        float wv = w[i];
        float b0 = sinf(wv * PI_F);
        b0 = fminf(fmaxf(b0, -1.f), 1.f);
        float bl = b0 + b0 * cosf((float)i * inv + THIRD_F) * 1.5f;
        float e = cosf(bl * PI2_F) + bl * bl * DEVPI_F;
        float a = fabsf(e);
        aout[i] = a;
        atomicAdd(&h[__float_as_uint(a) >> 20], 1u);
    }
    __syncthreads();
    for (int j = threadIdx.x; j < 4096; j += blockDim.x) {
        unsigned c = h[j];
        if (c) atomicAdd(&h1[j], c);
    }
}

__global__ void k_scan1_all(const float* ipw, const float* w1, const float* w2)
{
    int slot = blockIdx.x;
    int n; slot_w(slot, ipw, w1, w2, n);
    unsigned rA = (unsigned)((n - 1) >> 2);
    unsigned rB = rA + 1;
    const unsigned* h1 = d_h1g + slot * 4096;
    unsigned* sel = d_selg + slot * 8;

    __shared__ unsigned part[256];
    __shared__ unsigned pref[256];
    int t = threadIdx.x, base = t * 16;
    unsigned c[16]; unsigned s = 0;
    for (int j = 0; j < 16; j++) { c[j] = h1[base + j]; s += c[j]; }
    part[t] = s; __syncthreads();
    if (t == 0) { unsigned a = 0; for (int i = 0; i < 256; i++) { pref[i] = a; a += part[i]; } }
    __syncthreads();
    unsigned p = pref[t];
    for (int j = 0; j < 16; j++) {
        if (rA >= p && rA < p + c[j]) { sel[0] = base + j; sel[1] = rA - p; }
        if (rB >= p && rB < p + c[j]) { sel[2] = base + j; sel[3] = rB - p; }
        p += c[j];
    }
}

__global__ void k_hist2_all(const float* ipw, const float* w1, const float* w2)
{
    int slot = blockIdx.y;
    int n; slot_w(slot, ipw, w1, w2, n);
    const float* ab = d_abs_all + (size_t)slot * SLOT_STRIDE;
    const unsigned* sel = d_selg + slot * 8;
    unsigned* h2 = d_h2g + (size_t)slot * 131072;
    unsigned sA = sel[0], sB = sel[2];
    int stride = gridDim.x * blockDim.x;
    for (int i = blockIdx.x * blockDim.x + threadIdx.x; i < n; i += stride) {
        unsigned u = __float_as_uint(ab[i]);
        unsigned hi = u >> 20, mid = (u >> 4) & 0xFFFFu;
        if (hi == sA) atomicAdd(&h2[mid], 1u);
        if (hi == sB) atomicAdd(&h2[65536 + mid], 1u);
    }
}

__global__ void k_scan2_all()
{
    int slot = blockIdx.x;
    unsigned* sel = d_selg + slot * 8;
    __shared__ unsigned part[256];
    __shared__ unsigned pref[256];
    int t = threadIdx.x;
    for (int sidx = 0; sidx < 2; sidx++) {
        unsigned rank = sel[1 + sidx * 2];
        const unsigned* hb = d_h2g + (size_t)slot * 131072 + sidx * 65536;
        int base = t * 256;
        unsigned s = 0;
        for (int j = 0; j < 256; j++) s += hb[base + j];
        part[t] = s; __syncthreads();
        if (t == 0) { unsigned a = 0; for (int i = 0; i < 256; i++) { pref[i] = a; a += part[i]; } }
        __syncthreads();
        unsigned p = pref[t];
        for (int j = 0; j < 256; j++) {
            unsigned c = hb[base + j];
            if (rank >= p && rank < p + c) { sel[4 + sidx*2] = base + j; sel[5 + sidx*2] = rank - p; }
            p += c;
        }
        __syncthreads();
    }
}

__global__ void k_hist3_all(const float* ipw, const float* w1, const float* w2)
{
    int slot = blockIdx.y;
    int n; slot_w(slot, ipw, w1, w2, n);
    const float* ab = d_abs_all + (size_t)slot * SLOT_STRIDE;
    const unsigned* sel = d_selg + slot * 8;
    unsigned* h3 = d_h3g + slot * 32;
    unsigned kA = (sel[0] << 16) | sel[4];
    unsigned kB = (sel[2] << 16) | sel[6];
    int stride = gridDim.x * blockDim.x;
    for (int i = blockIdx.x * blockDim.x + threadIdx.x; i < n; i += stride) {
        unsigned u = __float_as_uint(ab[i]);
        unsigned top = u >> 4;
        if (top == kA) atomicAdd(&h3[u & 15u], 1u);
        if (top == kB) atomicAdd(&h3[16 + (u & 15u)], 1u);
    }
}

__global__ void k_thr_all(const float* ipw, const float* w1, const float* w2)
{
    int slot = blockIdx.x * blockDim.x + threadIdx.x;
    if (slot >= NSLOT) return;
    int n; slot_w(slot, ipw, w1, w2, n);
    float frac = 0.25f * (float)((n - 1) & 3);
    const unsigned* sel = d_selg + slot * 8;
    const unsigned* h3 = d_h3g + slot * 32;
    unsigned remA = sel[5]; unsigned lowA = 0;
    for (int j = 0; j < 16; j++) { unsigned c = h3[j]; if (remA < c) { lowA = j; break; } remA -= c; }
    unsigned remB = sel[7]; unsigned lowB = 0;
    for (int j = 0; j < 16; j++) { unsigned c = h3[16 + j]; if (remB < c) { lowB = j; break; } remB -= c; }
    float vA = __uint_as_float((sel[0] << 20) | (sel[4] << 4) | lowA);
    float vB = __uint_as_float((sel[2] << 20) | (sel[6] << 4) | lowB);
    d_thrg[slot] = vA + frac * (vB - vA);
}

__global__ void k_mask_all(const float* __restrict__ ipw, const float* __restrict__ w1,
                           const float* __restrict__ w2)
{
    int slot = blockIdx.y;
    int n;
    const float* w = slot_w(slot, ipw, w1, w2, n);
    int i = blockIdx.x * blockDim.x + threadIdx.x;
    if (i >= n) return;
    float thr = d_thrg[slot];
    d_wp[(size_t)slot * SLOT_STRIDE + i] =
        (d_abs_all[(size_t)slot * SLOT_STRIDE + i] > thr) ? tf32r(w[i]) : 0.f;
}

// ---------------- entry point ----------------
extern "C" void kernel_launch(void* const* d_in, const int* in_sizes, int n_in,
                              void* d_out, int out_size)
{
    const int*   src = (const int*)  d_in[0];
    const float* emb = (const float*)d_in[1];
    const float* pos = (const float*)d_in[2];
    const float* ipw = (const float*)d_in[3];
    const float* ipb = (const float*)d_in[4];
    const float* opw = (const float*)d_in[5];
    const float* opb = (const float*)d_in[6];
    const float* l1g = (const float*)d_in[7];
    const float* l1b = (const float*)d_in[8];
    const float* l2g = (const float*)d_in[9];
    const float* l2b = (const float*)d_in[10];
    const float* w1  = (const float*)d_in[11];
    const float* b1  = (const float*)d_in[12];
    const float* w2  = (const float*)d_in[13];
    const float* b2  = (const float*)d_in[14];
    const float* ow  = (const float*)d_in[15];
    const float* ob  = (const float*)d_in[16];
    const int V = in_sizes[16];
    float* out = (float*)d_out;

    float *px, *pxtf, *pqkv, *psc, *pao, *pff, *ptmp, *pwp, *pwr, *powr;
    cudaGetSymbolAddress((void**)&px,   d_x);
    cudaGetSymbolAddress((void**)&pxtf, d_xtf);
    cudaGetSymbolAddress((void**)&pqkv, d_qkv);
    cudaGetSymbolAddress((void**)&psc,  d_sc);
    cudaGetSymbolAddress((void**)&pao,  d_ao);
    cudaGetSymbolAddress((void**)&pff,  d_ff);
    cudaGetSymbolAddress((void**)&ptmp, d_tmp);
    cudaGetSymbolAddress((void**)&pwp,  d_wp);
    cudaGetSymbolAddress((void**)&pwr,  d_wr);
    cudaGetSymbolAddress((void**)&powr, d_owr);

    // Detect whether the tcgen05 body actually compiled for this device:
    // the guarded-out stub has a tiny register count.
    cudaFuncAttributes fa{};
    cudaFuncGetAttributes(&fa, k_tc<false,false,true>);
    const bool use_tc = fa.numRegs > 40;

    if (use_tc) {
        cudaFuncSetAttribute(k_tc<false,false,true >, cudaFuncAttributeMaxDynamicSharedMemorySize, TC_SMEM);
        cudaFuncSetAttribute(k_tc<false,false,false>, cudaFuncAttributeMaxDynamicSharedMemorySize, TC_SMEM);
        cudaFuncSetAttribute(k_tc<true ,false,true >, cudaFuncAttributeMaxDynamicSharedMemorySize, TC_SMEM);
        cudaFuncSetAttribute(k_tc<false,true ,false>, cudaFuncAttributeMaxDynamicSharedMemorySize, TC_SMEM);
    }

    k_embed<<<MT * D / 256, 256>>>(src, emb, pos, px, pxtf);
    k_round_w<<<(V * D + 255) / 256, 256>>>(opw, ow, V * D);

    k_zero_all<<<(NSLOT * 2 * 65536 + 255) / 256, 256>>>();
    k_etch_all <<<dim3(128, NSLOT), 256>>>(ipw, w1, w2);
    k_scan1_all<<<NSLOT, 256>>>(ipw, w1, w2);
    k_hist2_all<<<dim3(128, NSLOT), 256>>>(ipw, w1, w2);
    k_scan2_all<<<NSLOT, 256>>>();
    k_hist3_all<<<dim3(128, NSLOT), 256>>>(ipw, w1, w2);
    k_thr_all  <<<1, 32>>>(ipw, w1, w2);
    k_mask_all <<<dim3(4096, NSLOT), 256>>>(ipw, w1, w2);

    for (int l = 0; l < L; l++) {
        const float* wi_l = pwp + (size_t)(0 * 6 + l) * SLOT_STRIDE;
        const float* w1_l = pwp + (size_t)(1 * 6 + l) * SLOT_STRIDE;
        const float* w2_l = pwp + (size_t)(2 * 6 + l) * SLOT_STRIDE;

        // qkv = x @ wi^T + b (output tf32-rounded)
        if (use_tc)
            k_tc<false,false,true><<<dim3((3*D)/TC_BN, MT/TC_BM), 256, TC_SMEM>>>(
                3*D, D, pxtf, D, wi_l, D, pqkv, 3*D, ipb + (size_t)l * 3 * D);
        else
            k_mma<128,128,2,2,true,false,false,true><<<dim3((3*D)/128, MT/128, 1), 128>>>(
                MT, 3*D, D, pxtf, D, 0, 0, wi_l, D, 0, 0, pqkv, 3*D, 0, 0, 1,
                ipb + (size_t)l * 3 * D, 1.f);

        // scores = Q K^T / 8 (mma.sync, batched)
        k_mma<128,128,2,2,true,false,false,false><<<dim3(S/128, S/128, BH), 128>>>(
            S, S, DH,
            pqkv,     3*D, (long long)S*3*D, DH,
            pqkv + D, 3*D, (long long)S*3*D, DH,
            psc, S, (long long)H*S*S, (long long)S*S,
            H, nullptr, 0.125f);
        k_softmax<<<BH * S, 256>>>(psc);
        // o = att @ V (mma.sync, output rounded)
        k_mma<128,64,2,2,false,false,false,true><<<dim3(1, S/128, BH), 128>>>(
            S, DH, S,
            psc, S, (long long)H*S*S, (long long)S*S,
            pqkv + 2*D, 3*D, (long long)S*3*D, DH,
            pao, D, (long long)S*D, DH,
            H, nullptr, 1.f);

        // out projection
        if (use_tc)
            k_tc<false,false,false><<<dim3(D/TC_BN, MT/TC_BM), 256, TC_SMEM>>>(
                D, D, pao, D, pwr + (size_t)l*D*D, D, ptmp, D, opb + (size_t)l*D);
        else
            k_mma<128,128,2,2,true,false,false,false><<<dim3(D/128, MT/128, 1), 128>>>(
                MT, D, D, pao, D, 0, 0, pwr + (size_t)l*D*D, D, 0, 0,
                ptmp, D, 0, 0, 1, opb + (size_t)l*D, 1.f);
        k_add_ln<<<MT, 256>>>(px, ptmp, l1g + (size_t)l*D, l1b + (size_t)l*D, px, pxtf);

        // feed-forward
        if (use_tc) {
            k_tc<true,false,true><<<dim3(F/TC_BN, MT/TC_BM), 256, TC_SMEM>>>(
                F, D, pxtf, D, w1_l, D, pff, F, b1 + (size_t)l*F);
            k_tc<false,false,false><<<dim3(D/TC_BN, MT/TC_BM), 256, TC_SMEM>>>(
                D, F, pff, F, w2_l, F, ptmp, D, b2 + (size_t)l*D);
        } else {
            k_mma<128,128,2,2,true,true,false,true><<<dim3(F/128, MT/128, 1), 128>>>(
                MT, F, D, pxtf, D, 0, 0, w1_l, D, 0, 0, pff, F, 0, 0, 1,
                b1 + (size_t)l*F, 1.f);
            k_mma<128,128,2,2,true,false,false,false><<<dim3(D/128, MT/128, 1), 128>>>(
                MT, D, F, pff, F, 0, 0, w2_l, F, 0, 0, ptmp, D, 0, 0, 1,
                b2 + (size_t)l*D, 1.f);
        }
        k_add_ln<<<MT, 256>>>(px, ptmp, l2g + (size_t)l*D, l2b + (size_t)l*D, px, pxtf);
    }

    // logits
    if (use_tc)
        k_tc<false,true,false><<<dim3((V + TC_BN - 1)/TC_BN, MT/TC_BM), 256, TC_SMEM>>>(
            V, D, pxtf, D, powr, D, out, V, ob);
    else
        k_mma<128,128,2,2,true,false,true,false><<<dim3((V + 127) / 128, MT / 128, 1), 128>>>(
            MT, V, D, pxtf, D, 0, 0, powr, D, 0, 0, out, V, 0, 0, 1, ob, 1.f);
}

// round 6
// speedup vs baseline: 7.4544x; 1.4530x over previous
#include <cuda_runtime.h>
#include <cstdint>
#include <math.h>

// ---------------- constants ----------------
#define PI_F      3.14159265358979323846f
#define PI2_F     9.86960440108935861883f
#define THIRD_F   2.09439510239319549231f
#define DEVPI_F   0.003183098861837907f
#define SQRTD_F   22.62741699796952f

constexpr int S  = 512;
constexpr int D  = 512;
constexpr int H  = 8;
constexpr int DH = 64;
constexpr int L  = 6;
constexpr int F  = 2048;
constexpr int BB = 16;
constexpr int MT = BB * S;   // 8192 tokens
constexpr int BH = BB * H;   // 128
constexpr int NSLOT = 18;
constexpr size_t SLOT_STRIDE = 1048576;
constexpr int VMAX = 10240;

// Feature gate: tcgen05 only exists on arch-specific (sm_103a) / family (sm_103f) targets.
#if !defined(__CUDA_ARCH__) || defined(__CUDA_ARCH_FEAT_SM103_ALL) || defined(__CUDA_ARCH_SPECIFIC__) || defined(__CUDA_ARCH_FAMILY_SPECIFIC__)
#define TC_AVAIL 1
#else
#define TC_AVAIL 0
#endif

// ---------------- device scratch ----------------
__device__ __align__(128) float d_x   [MT * D];
__device__ __align__(128) float d_xtf [MT * D];
__device__ __align__(128) float d_qkv [MT * 3 * D];
__device__ __align__(128) float d_ao  [MT * D];
__device__ __align__(128) float d_ff  [MT * F];
__device__ __align__(128) float d_tmp [MT * D];
__device__ __align__(128) float d_wp  [NSLOT * SLOT_STRIDE];
__device__ __align__(128) float d_wr  [L * D * D];
__device__ __align__(128) float d_owr [VMAX * D];
__device__ __align__(128) float d_abs_all[NSLOT * SLOT_STRIDE];
__device__ unsigned d_h1g[NSLOT * 4096];
__device__ unsigned d_h2g[NSLOT * 2 * 65536];
__device__ unsigned d_h3g[NSLOT * 32];
__device__ unsigned d_selg[NSLOT * 8];
__device__ float d_thrg[NSLOT];

// ---------------- helpers ----------------
__device__ __forceinline__ float tf32r(float f) {
    uint32_t u;
    asm("cvt.rna.tf32.f32 %0, %1;" : "=r"(u) : "f"(f));
    return __uint_as_float(u);
}

__device__ __forceinline__ void mma_tf32(float c[4],
    uint32_t a0, uint32_t a1, uint32_t a2, uint32_t a3,
    uint32_t b0, uint32_t b1)
{
    asm volatile(
        "mma.sync.aligned.m16n8k8.row.col.f32.tf32.tf32.f32 "
        "{%0,%1,%2,%3}, {%4,%5,%6,%7}, {%8,%9}, {%0,%1,%2,%3};"
        : "+f"(c[0]), "+f"(c[1]), "+f"(c[2]), "+f"(c[3])
        : "r"(a0), "r"(a1), "r"(a2), "r"(a3), "r"(b0), "r"(b1));
}

__device__ __forceinline__ void cp16(void* d, const void* s) {
    uint32_t a = (uint32_t)__cvta_generic_to_shared(d);
    asm volatile("cp.async.cg.shared.global [%0], [%1], 16;" :: "r"(a), "l"(s));
}
__device__ __forceinline__ void cp16p(void* d, const void* s, bool p) {
    uint32_t a = (uint32_t)__cvta_generic_to_shared(d);
    int sz = p ? 16 : 0;
    asm volatile("cp.async.cg.shared.global [%0], [%1], 16, %2;" :: "r"(a), "l"(s), "r"(sz));
}
#define CP_COMMIT() asm volatile("cp.async.commit_group;")
#define CP_WAIT0()  asm volatile("cp.async.wait_group 0;")
#define CP_WAIT1()  asm volatile("cp.async.wait_group 1;")
#define CP_WAIT2()  asm volatile("cp.async.wait_group 2;")

// ================= tcgen05 tf32 GEMM (guarded) =================
constexpr int TC_BM = 128, TC_BN = 256, TC_BK = 32, TC_NS = 4;
constexpr int TC_ASZ = TC_BM * TC_BK * 4;       // 16384 (128 rows x 128B)
constexpr int TC_BSZ = TC_BN * TC_BK * 4;       // 32768 (256 rows x 128B)
constexpr int TC_SMEM = 1024 + TC_NS * (TC_ASZ + TC_BSZ);   // 197632

#if TC_AVAIL
__device__ __forceinline__ uint32_t elect1() {
    uint32_t pred;
    asm volatile("{\n\t.reg .pred p;\n\telect.sync _|p, 0xFFFFFFFF;\n\t"
                 "selp.b32 %0, 1, 0, p;\n\t}" : "=r"(pred));
    return pred;
}
#define MBAR_INIT(addr, cnt) \
    asm volatile("mbarrier.init.shared.b64 [%0], %1;" :: "r"(addr), "r"(cnt) : "memory")
#define MBAR_WAIT(addr, par) do { \
    asm volatile("{\n\t.reg .pred P1;\n\tWL%=:\n\t" \
        "mbarrier.try_wait.parity.acquire.cta.shared::cta.b64 P1, [%0], %1, 0x989680;\n\t" \
        "@P1 bra.uni WD%=;\n\tbra.uni WL%=;\n\tWD%=:\n\t}" \
        :: "r"(addr), "r"(par) : "memory"); \
} while (0)
#define TC_ALLOC(sm, n)   asm volatile("tcgen05.alloc.cta_group::1.sync.aligned.shared::cta.b32 [%0], %1;" :: "r"(sm), "r"(n) : "memory")
#define TC_DEALLOC(t, n)  asm volatile("tcgen05.dealloc.cta_group::1.sync.aligned.b32 %0, %1;" :: "r"(t), "r"(n))
#define TC_COMMIT(mb)     asm volatile("tcgen05.commit.cta_group::1.mbarrier::arrive::one.shared::cluster.b64 [%0];" :: "r"(mb) : "memory")
#define TC_FENCE_AFTER()  asm volatile("tcgen05.fence::after_thread_sync;" ::: "memory")
#define TC_FENCE_BEFORE() asm volatile("tcgen05.fence::before_thread_sync;" ::: "memory")
#define TC_WAIT_LD()      asm volatile("tcgen05.wait::ld.sync.aligned;" ::: "memory")
#define FENCE_PROXY()     asm volatile("fence.proxy.async.shared::cta;" ::: "memory")

#define TC_LD_X32(r, addr) \
    asm volatile("tcgen05.ld.sync.aligned.32x32b.x32.b32 " \
        "{%0, %1, %2, %3, %4, %5, %6, %7, %8, %9, %10, %11, %12, %13, %14, %15, " \
        " %16, %17, %18, %19, %20, %21, %22, %23, %24, %25, %26, %27, %28, %29, %30, %31}, [%32];" \
        : "=r"((r)[0]),  "=r"((r)[1]),  "=r"((r)[2]),  "=r"((r)[3]), \
          "=r"((r)[4]),  "=r"((r)[5]),  "=r"((r)[6]),  "=r"((r)[7]), \
          "=r"((r)[8]),  "=r"((r)[9]),  "=r"((r)[10]), "=r"((r)[11]), \
          "=r"((r)[12]), "=r"((r)[13]), "=r"((r)[14]), "=r"((r)[15]), \
          "=r"((r)[16]), "=r"((r)[17]), "=r"((r)[18]), "=r"((r)[19]), \
          "=r"((r)[20]), "=r"((r)[21]), "=r"((r)[22]), "=r"((r)[23]), \
          "=r"((r)[24]), "=r"((r)[25]), "=r"((r)[26]), "=r"((r)[27]), \
          "=r"((r)[28]), "=r"((r)[29]), "=r"((r)[30]), "=r"((r)[31]) \
        : "r"(addr))

static constexpr uint64_t SMEM_DESC_BASE =
    (uint64_t(2) << 61) | (uint64_t(1) << 46) | (uint64_t(64) << 32) | (uint64_t(1) << 16);
#define MK_DESC(a) (SMEM_DESC_BASE | ((uint64_t)((a) >> 4) & 0x3FFF))

__device__ __forceinline__ void mma_tc(uint32_t d, uint64_t ad, uint64_t bd,
                                       uint32_t idesc, bool en)
{
    uint32_t e = en ? 1 : 0;
    asm volatile(
        "{\n\t.reg .pred p;\n\tsetp.ne.u32 p, %4, 0;\n\t"
        "tcgen05.mma.cta_group::1.kind::tf32 [%0], %1, %2, %3, {%5,%5,%5,%5}, p;\n\t}"
        :: "r"(d), "l"(ad), "l"(bd), "r"(idesc), "r"(e), "r"(0u) : "memory");
}
#endif  // TC_AVAIL

constexpr uint32_t TC_IDESC =
    (1u << 4) | (2u << 7) | (2u << 10) | ((TC_BN / 8) << 17) | ((TC_BM / 16) << 24);

// C[m,n] = sum_k A[m,k]*B[n,k] + bias[n]; operands pre-rounded to tf32 values.
template<bool RELU, bool GN, bool TFO>
__global__ void __launch_bounds__(256, 1)
k_tc(int N, int K,
     const float* __restrict__ A, int lda,
     const float* __restrict__ B, int ldb,
     float* __restrict__ C, int ldc,
     const float* __restrict__ bias)
{
#if TC_AVAIL
    extern __shared__ char smem[];
    uint32_t sbase = (uint32_t)__cvta_generic_to_shared(smem);
    const int tid = threadIdx.x, lane = tid & 31, warp = tid >> 5;
    const int m0 = blockIdx.y * TC_BM, n0 = blockIdx.x * TC_BN;

    if (warp == 0) TC_ALLOC(sbase, 256);
    if (tid == 0) {
        #pragma unroll
        for (int s = 0; s < TC_NS; s++) MBAR_INIT(sbase + 16 + 8 * s, 1);
    }
    __syncthreads();
    uint32_t tmem;
    asm volatile("ld.shared.b32 %0, [%1];" : "=r"(tmem) : "r"(sbase));

    const uint32_t aoff = 1024, boff = 1024 + TC_NS * TC_ASZ;

    auto loadStage = [&](int st, int k0) {
        char* pa = smem + aoff + st * TC_ASZ;
        char* pb = smem + boff + st * TC_BSZ;
        #pragma unroll
        for (int r = 0; r < 4; r++) {
            int i = tid + r * 256;
            int m = i >> 3, c = i & 7;
            int cs = c ^ (m & 7);     // SW128
            cp16(pa + m * 128 + cs * 16, &A[(size_t)(m0 + m) * lda + k0 + c * 4]);
        }
        #pragma unroll
        for (int r = 0; r < 8; r++) {
            int i = tid + r * 256;
            int n = i >> 3, c = i & 7;
            int cs = c ^ (n & 7);
            int gn = n0 + n;
            if (GN) {
                bool ok = gn < N;
                cp16p(pb + n * 128 + cs * 16,
                      ok ? &B[(size_t)gn * ldb + k0 + c * 4] : (const float*)B, ok);
            } else {
                cp16(pb + n * 128 + cs * 16, &B[(size_t)gn * ldb + k0 + c * 4]);
            }
        }
    };

    const int nk = K / TC_BK;

    // prologue: 3 stages in flight (ring of 4)
    #pragma unroll
    for (int s = 0; s < 3; s++) { loadStage(s, s * TC_BK); CP_COMMIT(); }

    for (int kt = 0; kt < nk; kt++) {
        int cur = kt & 3;
        CP_WAIT2();               // stage kt data arrived (this thread)
        __syncthreads();          // all threads' data arrived
        FENCE_PROXY();
        if (warp == 0 && elect1()) {
            uint64_t ad = MK_DESC(sbase + aoff + cur * TC_ASZ);
            uint64_t bd = MK_DESC(sbase + boff + cur * TC_BSZ);
            #pragma unroll
            for (int j = 0; j < 4; j++)
                mma_tc(tmem, ad + j * 2, bd + j * 2, TC_IDESC, (kt > 0) || (j > 0));
            TC_COMMIT(sbase + 16 + 8 * cur);
        }
        // wait for MMA of kt-1 (its buffer is the one we load into next) — usually already done
        if (kt >= 1) MBAR_WAIT(sbase + 16 + 8 * ((kt - 1) & 3), ((kt - 1) / 4) & 1);
        int kn = kt + 3;
        if (kn < nk) loadStage(kn & 3, kn * TC_BK);
        CP_COMMIT();
    }
    // wait for the final MMA
    MBAR_WAIT(sbase + 16 + 8 * ((nk - 1) & 3), ((nk - 1) / 4) & 1);

    __syncthreads();
    TC_FENCE_AFTER();

    // epilogue: warp w reads its subpartition rows (w&3)*32..; cols split by w>>2
    float* myep = (float*)(smem + 1024) + warp * (32 * 33);
    int rbase = m0 + (warp & 3) * 32;
    int cbase = (warp >> 2) * 128;

    #pragma unroll
    for (int ch = 0; ch < 4; ch++) {
        int c0 = cbase + ch * 32;
        uint32_t regs[32];
        TC_LD_X32(regs, tmem + c0);
        TC_WAIT_LD();
        #pragma unroll
        for (int c = 0; c < 32; c++) {
            float v = __uint_as_float(regs[c]);
            if (!GN || (n0 + c0 + c) < N) {
                v += bias[n0 + c0 + c];
                if (RELU) v = fmaxf(v, 0.f);
                if (TFO)  v = tf32r(v);
            }
            myep[lane * 33 + c] = v;
        }
        __syncwarp();
        int col = n0 + c0 + lane;
        #pragma unroll
        for (int i = 0; i < 32; i++) {
            if (!GN || col < N)
                C[(size_t)(rbase + i) * ldc + col] = myep[i * 33 + lane];
        }
        __syncwarp();
    }

    __syncthreads();
    if (warp == 0) { TC_FENCE_BEFORE(); TC_DEALLOC(tmem, 256); }
#endif  // TC_AVAIL (else: empty stub — host detects via numRegs and falls back)
}

// ================= fused flash attention (mma.sync tf32) =================
// One block per (q-tile of 128 rows, bh). Streams 4 KV chunks of 128.
// qkv layout: [MT][1536], q at h*64, k at 512+h*64, v at 1024+h*64 (all tf32-rounded).
constexpr int AT_SMEM = 174080;

__global__ void __launch_bounds__(256, 1)
k_attn(const float* __restrict__ qkv, float* __restrict__ ao)
{
    extern __shared__ float sm_[];
    float* Qs   = sm_;               // [128][68]
    float* Ks   = Qs + 128 * 68;     // [128][68]
    float* Vs   = Ks + 128 * 68;     // [128][68]
    float* Ps   = Vs + 128 * 68;     // [128][132]
    float* rmx  = Ps + 128 * 132;    // [128][2]
    float* rsm  = rmx + 256;         // [128][2]

    const int tid = threadIdx.x, lane = tid & 31, warp = tid >> 5;
    const int wm = warp >> 1, wn = warp & 1;
    const int g = lane >> 2, t4 = lane & 3;
    const int bh = blockIdx.y, b = bh >> 3, h = bh & 7;
    const int qrow0 = b * 512 + blockIdx.x * 128;
    const int kvbase = b * 512;

    // load Q tile, pre-scaled by 1/8 (exact power of 2 -> stays tf32)
    #pragma unroll
    for (int r = 0; r < 8; r++) {
        int i = tid + r * 256;
        int row = i >> 4, c = (i & 15) << 2;
        float4 v = *(const float4*)&qkv[(size_t)(qrow0 + row) * 1536 + h * 64 + c];
        Qs[row * 68 + c]     = v.x * 0.125f;
        Qs[row * 68 + c + 1] = v.y * 0.125f;
        Qs[row * 68 + c + 2] = v.z * 0.125f;
        Qs[row * 68 + c + 3] = v.w * 0.125f;
    }

    float m_i[2][2], l_i[2][2];
    float oa[2][4][4];
    #pragma unroll
    for (int i = 0; i < 2; i++)
        #pragma unroll
        for (int hf = 0; hf < 2; hf++) { m_i[i][hf] = -1e30f; l_i[i][hf] = 0.f; }
    #pragma unroll
    for (int i = 0; i < 2; i++)
        #pragma unroll
        for (int j = 0; j < 4; j++)
            #pragma unroll
            for (int q = 0; q < 4; q++) oa[i][j][q] = 0.f;

    for (int kc = 0; kc < 4; kc++) {
        __syncthreads();    // Qs ready (kc=0) / Ks,Vs no longer read (kc>0)
        int kvrow0 = kvbase + kc * 128;
        #pragma unroll
        for (int r = 0; r < 8; r++) {
            int i = tid + r * 256;
            int row = i >> 4, c = (i & 15) << 2;
            cp16(&Ks[row * 68 + c], &qkv[(size_t)(kvrow0 + row) * 1536 + 512 + h * 64 + c]);
        }
        #pragma unroll
        for (int r = 0; r < 8; r++) {
            int i = tid + r * 256;
            int row = i >> 4, c = (i & 15) << 2;
            cp16(&Vs[row * 68 + c], &qkv[(size_t)(kvrow0 + row) * 1536 + 1024 + h * 64 + c]);
        }
        CP_COMMIT();
        CP_WAIT0();
        __syncthreads();

        // ---- S = Q Kt (scaled) : warp computes rows wm*32.., cols wn*64.. ----
        float s[2][8][4];
        #pragma unroll
        for (int i = 0; i < 2; i++)
            #pragma unroll
            for (int j = 0; j < 8; j++)
                #pragma unroll
                for (int q = 0; q < 4; q++) s[i][j][q] = 0.f;

        #pragma unroll
        for (int ks = 0; ks < 8; ks++) {
            uint32_t af[2][4], bf[8][2];
            #pragma unroll
            for (int i = 0; i < 2; i++) {
                int row = wm * 32 + i * 16 + g;
                af[i][0] = __float_as_uint(Qs[row * 68 + ks * 8 + t4]);
                af[i][1] = __float_as_uint(Qs[(row + 8) * 68 + ks * 8 + t4]);
                af[i][2] = __float_as_uint(Qs[row * 68 + ks * 8 + t4 + 4]);
                af[i][3] = __float_as_uint(Qs[(row + 8) * 68 + ks * 8 + t4 + 4]);
            }
            #pragma unroll
            for (int j = 0; j < 8; j++) {
                int nc = wn * 64 + j * 8 + g;
                bf[j][0] = __float_as_uint(Ks[nc * 68 + ks * 8 + t4]);
                bf[j][1] = __float_as_uint(Ks[nc * 68 + ks * 8 + t4 + 4]);
            }
            #pragma unroll
            for (int i = 0; i < 2; i++)
                #pragma unroll
                for (int j = 0; j < 8; j++)
                    mma_tf32(s[i][j], af[i][0], af[i][1], af[i][2], af[i][3],
                             bf[j][0], bf[j][1]);
        }

        // ---- online softmax: row max across 64 cols then across the 2 col-warps ----
        float mn[2][2];
        #pragma unroll
        for (int i = 0; i < 2; i++)
            #pragma unroll
            for (int hf = 0; hf < 2; hf++) {
                float v = -1e30f;
                #pragma unroll
                for (int j = 0; j < 8; j++)
                    v = fmaxf(v, fmaxf(s[i][j][2 * hf], s[i][j][2 * hf + 1]));
                v = fmaxf(v, __shfl_xor_sync(0xFFFFFFFF, v, 1));
                v = fmaxf(v, __shfl_xor_sync(0xFFFFFFFF, v, 2));
                mn[i][hf] = v;
            }
        if (t4 == 0) {
            #pragma unroll
            for (int i = 0; i < 2; i++)
                #pragma unroll
                for (int hf = 0; hf < 2; hf++)
                    rmx[(wm * 32 + i * 16 + g + 8 * hf) * 2 + wn] = mn[i][hf];
        }
        __syncthreads();
        float sc[2][2];
        #pragma unroll
        for (int i = 0; i < 2; i++)
            #pragma unroll
            for (int hf = 0; hf < 2; hf++) {
                int row = wm * 32 + i * 16 + g + 8 * hf;
                float cm = fmaxf(rmx[row * 2], rmx[row * 2 + 1]);
                float nm = fmaxf(m_i[i][hf], cm);
                sc[i][hf] = __expf(m_i[i][hf] - nm);
                mn[i][hf] = nm;
            }
        // rescale accumulator
        #pragma unroll
        for (int i = 0; i < 2; i++)
            #pragma unroll
            for (int j = 0; j < 4; j++) {
                oa[i][j][0] *= sc[i][0]; oa[i][j][1] *= sc[i][0];
                oa[i][j][2] *= sc[i][1]; oa[i][j][3] *= sc[i][1];
            }
        // P = exp(S - mn), partial sums, stage tf32-rounded P
        float smv[2][2] = {{0.f, 0.f}, {0.f, 0.f}};
        #pragma unroll
        for (int i = 0; i < 2; i++) {
            int row = wm * 32 + i * 16 + g;
            #pragma unroll
            for (int j = 0; j < 8; j++) {
                int col = wn * 64 + j * 8 + 2 * t4;
                float p0 = __expf(s[i][j][0] - mn[i][0]);
                float p1 = __expf(s[i][j][1] - mn[i][0]);
                float p2 = __expf(s[i][j][2] - mn[i][1]);
                float p3 = __expf(s[i][j][3] - mn[i][1]);
                smv[i][0] += p0 + p1;
                smv[i][1] += p2 + p3;
                Ps[row * 132 + col]           = tf32r(p0);
                Ps[row * 132 + col + 1]       = tf32r(p1);
                Ps[(row + 8) * 132 + col]     = tf32r(p2);
                Ps[(row + 8) * 132 + col + 1] = tf32r(p3);
            }
        }
        #pragma unroll
        for (int i = 0; i < 2; i++)
            #pragma unroll
            for (int hf = 0; hf < 2; hf++) {
                float v = smv[i][hf];
                v += __shfl_xor_sync(0xFFFFFFFF, v, 1);
                v += __shfl_xor_sync(0xFFFFFFFF, v, 2);
                smv[i][hf] = v;
            }
        if (t4 == 0) {
            #pragma unroll
            for (int i = 0; i < 2; i++)
                #pragma unroll
                for (int hf = 0; hf < 2; hf++)
                    rsm[(wm * 32 + i * 16 + g + 8 * hf) * 2 + wn] = smv[i][hf];
        }
        __syncthreads();   // P staged + row sums ready
        #pragma unroll
        for (int i = 0; i < 2; i++)
            #pragma unroll
            for (int hf = 0; hf < 2; hf++) {
                int row = wm * 32 + i * 16 + g + 8 * hf;
                l_i[i][hf] = l_i[i][hf] * sc[i][hf] + rsm[row * 2] + rsm[row * 2 + 1];
                m_i[i][hf] = mn[i][hf];
            }

        // ---- O += P · V : rows wm*32.., cols wn*32.., K = 128 ----
        #pragma unroll
        for (int ks = 0; ks < 16; ks++) {
            uint32_t af[2][4], bf[4][2];
            #pragma unroll
            for (int i = 0; i < 2; i++) {
                int row = wm * 32 + i * 16 + g;
                af[i][0] = __float_as_uint(Ps[row * 132 + ks * 8 + t4]);
                af[i][1] = __float_as_uint(Ps[(row + 8) * 132 + ks * 8 + t4]);
                af[i][2] = __float_as_uint(Ps[row * 132 + ks * 8 + t4 + 4]);
                af[i][3] = __float_as_uint(Ps[(row + 8) * 132 + ks * 8 + t4 + 4]);
            }
            #pragma unroll
            for (int j = 0; j < 4; j++) {
                int nc = wn * 32 + j * 8 + g;
                bf[j][0] = __float_as_uint(Vs[(ks * 8 + t4) * 68 + nc]);
                bf[j][1] = __float_as_uint(Vs[(ks * 8 + t4 + 4) * 68 + nc]);
            }
            #pragma unroll
            for (int i = 0; i < 2; i++)
                #pragma unroll
                for (int j = 0; j < 4; j++)
                    mma_tf32(oa[i][j], af[i][0], af[i][1], af[i][2], af[i][3],
                             bf[j][0], bf[j][1]);
        }
    }

    // ---- write O = acc / l (tf32-rounded; feeds out_proj GEMM) ----
    #pragma unroll
    for (int i = 0; i < 2; i++) {
        float r0 = 1.f / l_i[i][0], r1 = 1.f / l_i[i][1];
        int row = qrow0 + wm * 32 + i * 16 + g;
        #pragma unroll
        for (int j = 0; j < 4; j++) {
            int col = h * 64 + wn * 32 + j * 8 + 2 * t4;
            *(float2*)&ao[(size_t)row * 512 + col] =
                make_float2(tf32r(oa[i][j][0] * r0), tf32r(oa[i][j][1] * r0));
            *(float2*)&ao[(size_t)(row + 8) * 512 + col] =
                make_float2(tf32r(oa[i][j][2] * r1), tf32r(oa[i][j][3] * r1));
        }
    }
}

// ================= mma.sync GEMM (fallback path) =================
template<int BM,int BN,int WARPS_M,int WARPS_N,bool TB,bool RELU,bool GN,bool TFO>
__global__ void __launch_bounds__(WARPS_M*WARPS_N*32)
k_mma(int M, int N, int K,
      const float* __restrict__ Ag, int lda, long long sA1, long long sA2,
      const float* __restrict__ Bg, int ldb, long long sB1, long long sB2,
      float* __restrict__ Cg, int ldc, long long sC1, long long sC2,
      int zdiv, const float* __restrict__ bias, float alpha)
{
    constexpr int BK = 16;
    constexpr int NT = WARPS_M * WARPS_N * 32;
    constexpr int WM = BM / WARPS_M, WN = BN / WARPS_N;
    constexpr int MI = WM / 16, NI = WN / 8;
    constexpr int AST = BK + 4;
    constexpr int BROWS = TB ? BN : BK;
    constexpr int BCOLS = TB ? (BK + 4) : (BN + 8);

    __shared__ __align__(16) float As[2][BM][AST];
    __shared__ __align__(16) float Bs[2][BROWS][BCOLS];

    const int bz = blockIdx.z;
    const int z1 = bz / zdiv, z2 = bz - z1 * zdiv;
    const float* A  = Ag + z1 * sA1 + z2 * sA2;
    const float* Bp = Bg + z1 * sB1 + z2 * sB2;
    float* C        = Cg + z1 * sC1 + z2 * sC2;

    const int m0 = blockIdx.y * BM, n0 = blockIdx.x * BN;
    const int tid  = threadIdx.x;
    const int lane = tid & 31, warp = tid >> 5;
    const int wm = warp / WARPS_N, wn = warp - wm * WARPS_N;
    const int g = lane >> 2, t4 = lane & 3;

    float acc[MI][NI][4];
    #pragma unroll
    for (int i = 0; i < MI; i++)
        #pragma unroll
        for (int j = 0; j < NI; j++)
            #pragma unroll
            for (int q = 0; q < 4; q++) acc[i][j][q] = 0.f;

    auto loadTiles = [&](int st, int k0) {
        #pragma unroll
        for (int r = 0; r < (BM * (BK/4)) / NT; r++) {
            int i = tid + r * NT;
            int m = i >> 2;
            int c = (i & 3) << 2;
            cp16(&As[st][m][c], &A[(size_t)(m0 + m) * lda + k0 + c]);
        }
        if (TB) {
            #pragma unroll
            for (int r = 0; r < (BN * (BK/4)) / NT; r++) {
                int i = tid + r * NT;
                int n = i >> 2;
                int c = (i & 3) << 2;
                int gn = n0 + n;
                if (GN) {
                    bool ok = gn < N;
                    cp16p(&Bs[st][n][c], ok ? &Bp[(size_t)gn * ldb + k0 + c] : (const float*)Bp, ok);
                } else {
                    cp16(&Bs[st][n][c], &Bp[(size_t)gn * ldb + k0 + c]);
                }
            }
        } else {
            #pragma unroll
            for (int r = 0; r < (BK * (BN/4)) / NT; r++) {
                int i = tid + r * NT;
                int kk = i / (BN/4);
                int c  = (i - kk * (BN/4)) << 2;
                cp16(&Bs[st][kk][c], &Bp[(size_t)(k0 + kk) * ldb + n0 + c]);
            }
        }
    };

    const int nk = K / BK;
    loadTiles(0, 0);
    CP_COMMIT();

    for (int kt = 0; kt < nk; kt++) {
        int cur = kt & 1;
        if (kt + 1 < nk) loadTiles(cur ^ 1, (kt + 1) * BK);
        CP_COMMIT();
        CP_WAIT1();
        __syncthreads();

        #pragma unroll
        for (int ks = 0; ks < 2; ks++) {
            uint32_t af[MI][4], bf[NI][2];
            #pragma unroll
            for (int i = 0; i < MI; i++) {
                int mr = wm * WM + i * 16 + g;
                af[i][0] = __float_as_uint(As[cur][mr    ][ks*8 + t4    ]);
                af[i][1] = __float_as_uint(As[cur][mr + 8][ks*8 + t4    ]);
                af[i][2] = __float_as_uint(As[cur][mr    ][ks*8 + t4 + 4]);
                af[i][3] = __float_as_uint(As[cur][mr + 8][ks*8 + t4 + 4]);
            }
            #pragma unroll
            for (int j = 0; j < NI; j++) {
                int nc = wn * WN + j * 8 + g;
                if (TB) {
                    bf[j][0] = __float_as_uint(Bs[cur][nc][ks*8 + t4    ]);
                    bf[j][1] = __float_as_uint(Bs[cur][nc][ks*8 + t4 + 4]);
                } else {
                    bf[j][0] = __float_as_uint(Bs[cur][ks*8 + t4    ][nc]);
                    bf[j][1] = __float_as_uint(Bs[cur][ks*8 + t4 + 4][nc]);
                }
            }
            #pragma unroll
            for (int i = 0; i < MI; i++)
                #pragma unroll
                for (int j = 0; j < NI; j++)
                    mma_tf32(acc[i][j], af[i][0], af[i][1], af[i][2], af[i][3],
                             bf[j][0], bf[j][1]);
        }
        __syncthreads();
    }

    #pragma unroll
    for (int i = 0; i < MI; i++) {
        int r0 = m0 + wm * WM + i * 16 + g;
        #pragma unroll
        for (int j = 0; j < NI; j++) {
            int col = n0 + wn * WN + j * 8 + t4 * 2;
            if (GN && col >= N) continue;
            float b0v = 0.f, b1v = 0.f;
            if (bias) { b0v = bias[col]; b1v = bias[col + 1]; }
            float v0 = acc[i][j][0] * alpha + b0v;
            float v1 = acc[i][j][1] * alpha + b1v;
            float v2 = acc[i][j][2] * alpha + b0v;
            float v3 = acc[i][j][3] * alpha + b1v;
            if (RELU) {
                v0 = fmaxf(v0, 0.f); v1 = fmaxf(v1, 0.f);
                v2 = fmaxf(v2, 0.f); v3 = fmaxf(v3, 0.f);
            }
            if (TFO) {
                v0 = tf32r(v0); v1 = tf32r(v1); v2 = tf32r(v2); v3 = tf32r(v3);
            }
            *reinterpret_cast<float2*>(&C[(size_t)r0 * ldc + col])       = make_float2(v0, v1);
            *reinterpret_cast<float2*>(&C[(size_t)(r0 + 8) * ldc + col]) = make_float2(v2, v3);
        }
    }
}

// ---------------- residual add + layernorm ----------------
__global__ void k_add_ln(const float* __restrict__ xin, const float* __restrict__ res,
                         const float* __restrict__ g, const float* __restrict__ b,
                         float* __restrict__ xout, float* __restrict__ xtf)
{
    int row = blockIdx.x, t = threadIdx.x;
    long long base = (long long)row * D;
    float v0 = xin[base + t]       + res[base + t];
    float v1 = xin[base + t + 256] + res[base + t + 256];
    __shared__ float red[256];
    red[t] = v0 + v1; __syncthreads();
    for (int o = 128; o > 0; o >>= 1) { if (t < o) red[t] += red[t+o]; __syncthreads(); }
    float mean = red[0] * (1.f / D); __syncthreads();
    red[t] = v0*v0 + v1*v1; __syncthreads();
    for (int o = 128; o > 0; o >>= 1) { if (t < o) red[t] += red[t+o]; __syncthreads(); }
    float var = red[0] * (1.f / D) - mean*mean;
    float rs = rsqrtf(var + 1e-5f);
    float o0 = (v0 - mean) * rs * g[t]       + b[t];
    float o1 = (v1 - mean) * rs * g[t + 256] + b[t + 256];
    xout[base + t]       = o0;
    xout[base + t + 256] = o1;
    xtf [base + t]       = tf32r(o0);
    xtf [base + t + 256] = tf32r(o1);
}

// ---------------- embedding ----------------
__global__ void k_embed(const int* __restrict__ src, const float* __restrict__ emb,
                        const float* __restrict__ pos, float* __restrict__ x,
                        float* __restrict__ xtf)
{
    int idx = blockIdx.x * blockDim.x + threadIdx.x;
    int t = idx >> 9, d = idx & 511;
    float v = emb[(long long)src[t] * D + d] * SQRTD_F + pos[(t & 511) * D + d];
    x[idx]   = v;
    xtf[idx] = tf32r(v);
}

// ---------------- round static weights ----------------
__global__ void k_round_w(const float* __restrict__ opw, const float* __restrict__ ow, int nOw)
{
    int i = blockIdx.x * blockDim.x + threadIdx.x;
    if (i < L * D * D) d_wr[i] = tf32r(opw[i]);
    if (i < nOw)       d_owr[i] = tf32r(ow[i]);
}

// ---------------- batched prune pipeline ----------------
__device__ __forceinline__ const float* slot_w(int slot, const float* ipw,
                                               const float* w1, const float* w2, int& n)
{
    int t = slot / 6, l = slot - t * 6;
    if (t == 0) { n = 3 * D * D; return ipw + (size_t)l * 3 * D * D; }
    n = F * D;
    return (t == 1) ? w1 + (size_t)l * F * D : w2 + (size_t)l * F * D;
}

__global__ void k_zero_all()
{
    int i = blockIdx.x * blockDim.x + threadIdx.x;
    if (i < NSLOT * 2 * 65536) d_h2g[i] = 0;
    if (i < NSLOT * 4096)      d_h1g[i] = 0;
    if (i < NSLOT * 32)        d_h3g[i] = 0;
}

__global__ void k_etch_all(const float* __restrict__ ipw, const float* __restrict__ w1,
                           const float* __restrict__ w2)
{
    int slot = blockIdx.y;
    int n;
    const float* w = slot_w(slot, ipw, w1, w2, n);
    float inv = 1.f / (float)(n - 1);
    float* aout = d_abs_all + (size_t)slot * SLOT_STRIDE;
    unsigned* h1 = d_h1g + slot * 4096;

    __shared__ unsigned h[4096];
    for (int j = threadIdx.x; j < 4096; j += blockDim.x) h[j] = 0;
    __syncthreads();
    int stride = gridDim.x * blockDim.x;
    for (int i = blockIdx.x * blockDim.x + threadIdx.x; i < n; i += stride) {
        float wv = w[i];
        float b0 = sinf(wv * PI_F);
        b0 = fminf(fmaxf(b0, -1.f), 1.f);
        float bl = b0 + b0 * cosf((float)i * inv + THIRD_F) * 1.5f;
        float e = cosf(bl * PI2_F) + bl * bl * DEVPI_F;
        float a = fabsf(e);
        aout[i] = a;
        atomicAdd(&h[__float_as_uint(a) >> 20], 1u);
    }
    __syncthreads();
    for (int j = threadIdx.x; j < 4096; j += blockDim.x) {
        unsigned c = h[j];
        if (c) atomicAdd(&h1[j], c);
    }
}

__global__ void k_scan1_all(const float* ipw, const float* w1, const float* w2)
{
    int slot = blockIdx.x;
    int n; slot_w(slot, ipw, w1, w2, n);
    unsigned rA = (unsigned)((n - 1) >> 2);
    unsigned rB = rA + 1;
    const unsigned* h1 = d_h1g + slot * 4096;
    unsigned* sel = d_selg + slot * 8;

    __shared__ unsigned part[256];
    __shared__ unsigned pref[256];
    int t = threadIdx.x, base = t * 16;
    unsigned c[16]; unsigned s = 0;
    for (int j = 0; j < 16; j++) { c[j] = h1[base + j]; s += c[j]; }
    part[t] = s; __syncthreads();
    if (t == 0) { unsigned a = 0; for (int i = 0; i < 256; i++) { pref[i] = a; a += part[i]; } }
    __syncthreads();
    unsigned p = pref[t];
    for (int j = 0; j < 16; j++) {
        if (rA >= p && rA < p + c[j]) { sel[0] = base + j; sel[1] = rA - p; }
        if (rB >= p && rB < p + c[j]) { sel[2] = base + j; sel[3] = rB - p; }
        p += c[j];
    }
}

__global__ void k_hist2_all(const float* ipw, const float* w1, const float* w2)
{
    int slot = blockIdx.y;
    int n; slot_w(slot, ipw, w1, w2, n);
    const float* ab = d_abs_all + (size_t)slot * SLOT_STRIDE;
    const unsigned* sel = d_selg + slot * 8;
    unsigned* h2 = d_h2g + (size_t)slot * 131072;
    unsigned sA = sel[0], sB = sel[2];
    int stride = gridDim.x * blockDim.x;
    for (int i = blockIdx.x * blockDim.x + threadIdx.x; i < n; i += stride) {
        unsigned u = __float_as_uint(ab[i]);
        unsigned hi = u >> 20, mid = (u >> 4) & 0xFFFFu;
        if (hi == sA) atomicAdd(&h2[mid], 1u);
        if (hi == sB) atomicAdd(&h2[65536 + mid], 1u);
    }
}

__global__ void k_scan2_all()
{
    int slot = blockIdx.x;
    unsigned* sel = d_selg + slot * 8;
    __shared__ unsigned part[256];
    __shared__ unsigned pref[256];
    int t = threadIdx.x;
    for (int sidx = 0; sidx < 2; sidx++) {
        unsigned rank = sel[1 + sidx * 2];
        const unsigned* hb = d_h2g + (size_t)slot * 131072 + sidx * 65536;
        int base = t * 256;
        unsigned s = 0;
        for (int j = 0; j < 256; j++) s += hb[base + j];
        part[t] = s; __syncthreads();
        if (t == 0) { unsigned a = 0; for (int i = 0; i < 256; i++) { pref[i] = a; a += part[i]; } }
        __syncthreads();
        unsigned p = pref[t];
        for (int j = 0; j < 256; j++) {
            unsigned c = hb[base + j];
            if (rank >= p && rank < p + c) { sel[4 + sidx*2] = base + j; sel[5 + sidx*2] = rank - p; }
            p += c;
        }
        __syncthreads();
    }
}

__global__ void k_hist3_all(const float* ipw, const float* w1, const float* w2)
{
    int slot = blockIdx.y;
    int n; slot_w(slot, ipw, w1, w2, n);
    const float* ab = d_abs_all + (size_t)slot * SLOT_STRIDE;
    const unsigned* sel = d_selg + slot * 8;
    unsigned* h3 = d_h3g + slot * 32;
    unsigned kA = (sel[0] << 16) | sel[4];
    unsigned kB = (sel[2] << 16) | sel[6];
    int stride = gridDim.x * blockDim.x;
    for (int i = blockIdx.x * blockDim.x + threadIdx.x; i < n; i += stride) {
        unsigned u = __float_as_uint(ab[i]);
        unsigned top = u >> 4;
        if (top == kA) atomicAdd(&h3[u & 15u], 1u);
        if (top == kB) atomicAdd(&h3[16 + (u & 15u)], 1u);
    }
}

__global__ void k_thr_all(const float* ipw, const float* w1, const float* w2)
{
    int slot = blockIdx.x * blockDim.x + threadIdx.x;
    if (slot >= NSLOT) return;
    int n; slot_w(slot, ipw, w1, w2, n);
    float frac = 0.25f * (float)((n - 1) & 3);
    const unsigned* sel = d_selg + slot * 8;
    const unsigned* h3 = d_h3g + slot * 32;
    unsigned remA = sel[5]; unsigned lowA = 0;
    for (int j = 0; j < 16; j++) { unsigned c = h3[j]; if (remA < c) { lowA = j; break; } remA -= c; }
    unsigned remB = sel[7]; unsigned lowB = 0;
    for (int j = 0; j < 16; j++) { unsigned c = h3[16 + j]; if (remB < c) { lowB = j; break; } remB -= c; }
    float vA = __uint_as_float((sel[0] << 20) | (sel[4] << 4) | lowA);
    float vB = __uint_as_float((sel[2] << 20) | (sel[6] << 4) | lowB);
    d_thrg[slot] = vA + frac * (vB - vA);
}

__global__ void k_mask_all(const float* __restrict__ ipw, const float* __restrict__ w1,
                           const float* __restrict__ w2)
{
    int slot = blockIdx.y;
    int n;
    const float* w = slot_w(slot, ipw, w1, w2, n);
    int i = blockIdx.x * blockDim.x + threadIdx.x;
    if (i >= n) return;
    float thr = d_thrg[slot];
    d_wp[(size_t)slot * SLOT_STRIDE + i] =
        (d_abs_all[(size_t)slot * SLOT_STRIDE + i] > thr) ? tf32r(w[i]) : 0.f;
}

// ---------------- entry point ----------------
extern "C" void kernel_launch(void* const* d_in, const int* in_sizes, int n_in,
                              void* d_out, int out_size)
{
    const int*   src = (const int*)  d_in[0];
    const float* emb = (const float*)d_in[1];
    const float* pos = (const float*)d_in[2];
    const float* ipw = (const float*)d_in[3];
    const float* ipb = (const float*)d_in[4];
    const float* opw = (const float*)d_in[5];
    const float* opb = (const float*)d_in[6];
    const float* l1g = (const float*)d_in[7];
    const float* l1b = (const float*)d_in[8];
    const float* l2g = (const float*)d_in[9];
    const float* l2b = (const float*)d_in[10];
    const float* w1  = (const float*)d_in[11];
    const float* b1  = (const float*)d_in[12];
    const float* w2  = (const float*)d_in[13];
    const float* b2  = (const float*)d_in[14];
    const float* ow  = (const float*)d_in[15];
    const float* ob  = (const float*)d_in[16];
    const int V = in_sizes[16];
    float* out = (float*)d_out;

    float *px, *pxtf, *pqkv, *pao, *pff, *ptmp, *pwp, *pwr, *powr;
    cudaGetSymbolAddress((void**)&px,   d_x);
    cudaGetSymbolAddress((void**)&pxtf, d_xtf);
    cudaGetSymbolAddress((void**)&pqkv, d_qkv);
    cudaGetSymbolAddress((void**)&pao,  d_ao);
    cudaGetSymbolAddress((void**)&pff,  d_ff);
    cudaGetSymbolAddress((void**)&ptmp, d_tmp);
    cudaGetSymbolAddress((void**)&pwp,  d_wp);
    cudaGetSymbolAddress((void**)&pwr,  d_wr);
    cudaGetSymbolAddress((void**)&powr, d_owr);

    cudaFuncAttributes fa{};
    cudaFuncGetAttributes(&fa, k_tc<false,false,true>);
    const bool use_tc = fa.numRegs > 40;

    if (use_tc) {
        cudaFuncSetAttribute(k_tc<false,false,true >, cudaFuncAttributeMaxDynamicSharedMemorySize, TC_SMEM);
        cudaFuncSetAttribute(k_tc<false,false,false>, cudaFuncAttributeMaxDynamicSharedMemorySize, TC_SMEM);
        cudaFuncSetAttribute(k_tc<true ,false,true >, cudaFuncAttributeMaxDynamicSharedMemorySize, TC_SMEM);
        cudaFuncSetAttribute(k_tc<false,true ,false>, cudaFuncAttributeMaxDynamicSharedMemorySize, TC_SMEM);
    }
    cudaFuncSetAttribute(k_attn, cudaFuncAttributeMaxDynamicSharedMemorySize, AT_SMEM);

    k_embed<<<MT * D / 256, 256>>>(src, emb, pos, px, pxtf);
    k_round_w<<<(V * D + 255) / 256, 256>>>(opw, ow, V * D);

    k_zero_all<<<(NSLOT * 2 * 65536 + 255) / 256, 256>>>();
    k_etch_all <<<dim3(128, NSLOT), 256>>>(ipw, w1, w2);
    k_scan1_all<<<NSLOT, 256>>>(ipw, w1, w2);
    k_hist2_all<<<dim3(128, NSLOT), 256>>>(ipw, w1, w2);
    k_scan2_all<<<NSLOT, 256>>>();
    k_hist3_all<<<dim3(128, NSLOT), 256>>>(ipw, w1, w2);
    k_thr_all  <<<1, 32>>>(ipw, w1, w2);
    k_mask_all <<<dim3(4096, NSLOT), 256>>>(ipw, w1, w2);

    for (int l = 0; l < L; l++) {
        const float* wi_l = pwp + (size_t)(0 * 6 + l) * SLOT_STRIDE;
        const float* w1_l = pwp + (size_t)(1 * 6 + l) * SLOT_STRIDE;
        const float* w2_l = pwp + (size_t)(2 * 6 + l) * SLOT_STRIDE;

        // qkv = x @ wi^T + b (output tf32-rounded: feeds attention)
        if (use_tc)
            k_tc<false,false,true><<<dim3((3*D)/TC_BN, MT/TC_BM), 256, TC_SMEM>>>(
                3*D, D, pxtf, D, wi_l, D, pqkv, 3*D, ipb + (size_t)l * 3 * D);
        else
            k_mma<128,128,2,2,true,false,false,true><<<dim3((3*D)/128, MT/128, 1), 128>>>(
                MT, 3*D, D, pxtf, D, 0, 0, wi_l, D, 0, 0, pqkv, 3*D, 0, 0, 1,
                ipb + (size_t)l * 3 * D, 1.f);

        // fused flash attention: scores + softmax + AV in one kernel
        k_attn<<<dim3(4, BH), 256, AT_SMEM>>>(pqkv, pao);

        // out projection
        if (use_tc)
            k_tc<false,false,false><<<dim3(D/TC_BN, MT/TC_BM), 256, TC_SMEM>>>(
                D, D, pao, D, pwr + (size_t)l*D*D, D, ptmp, D, opb + (size_t)l*D);
        else
            k_mma<128,128,2,2,true,false,false,false><<<dim3(D/128, MT/128, 1), 128>>>(
                MT, D, D, pao, D, 0, 0, pwr + (size_t)l*D*D, D, 0, 0,
                ptmp, D, 0, 0, 1, opb + (size_t)l*D, 1.f);
        k_add_ln<<<MT, 256>>>(px, ptmp, l1g + (size_t)l*D, l1b + (size_t)l*D, px, pxtf);

        // feed-forward
        if (use_tc) {
            k_tc<true,false,true><<<dim3(F/TC_BN, MT/TC_BM), 256, TC_SMEM>>>(
                F, D, pxtf, D, w1_l, D, pff, F, b1 + (size_t)l*F);
            k_tc<false,false,false><<<dim3(D/TC_BN, MT/TC_BM), 256, TC_SMEM>>>(
                D, F, pff, F, w2_l, F, ptmp, D, b2 + (size_t)l*D);
        } else {
            k_mma<128,128,2,2,true,true,false,true><<<dim3(F/128, MT/128, 1), 128>>>(
                MT, F, D, pxtf, D, 0, 0, w1_l, D, 0, 0, pff, F, 0, 0, 1,
                b1 + (size_t)l*F, 1.f);
            k_mma<128,128,2,2,true,false,false,false><<<dim3(D/128, MT/128, 1), 128>>>(
                MT, D, F, pff, F, 0, 0, w2_l, F, 0, 0, ptmp, D, 0, 0, 1,
                b2 + (size_t)l*D, 1.f);
        }
        k_add_ln<<<MT, 256>>>(px, ptmp, l2g + (size_t)l*D, l2b + (size_t)l*D, px, pxtf);
    }

    // logits
    if (use_tc)
        k_tc<false,true,false><<<dim3((V + TC_BN - 1)/TC_BN, MT/TC_BM), 256, TC_SMEM>>>(
            V, D, pxtf, D, powr, D, out, V, ob);
    else
        k_mma<128,128,2,2,true,false,true,false><<<dim3((V + 127) / 128, MT / 128, 1), 128>>>(
            MT, V, D, pxtf, D, 0, 0, powr, D, 0, 0, out, V, 0, 0, 1, ob, 1.f);
}